// round 2
// baseline (speedup 1.0000x reference)
#include <cuda_runtime.h>
#include <cuda_bf16.h>
#include <cstddef>

// Problem constants
#define S_TOT  8192
#define HID    1152
#define NH     16
#define HD     72
#define NSEG   8
#define LSEG   1024
#define H3     3456
#define ATT_SCALE 0.11785113019775793f   // 72^-0.5

// Scratch (allocation-free rule: __device__ globals)
__device__ float g_qkv[(size_t)S_TOT * H3];   // 113 MB
__device__ float g_ctx[(size_t)S_TOT * HID];  // 37.7 MB

// ---------------------------------------------------------------------------
// SGEMM with fused bias: C[M,N] = A[M,K] @ B[K,N] + bias[N]
// 128x128 block tile, BK=8, 256 threads, 8x8 per thread, register prefetch.
// (Measured 160 TFLOP/s fp32 in R1 — keep as-is.)
// ---------------------------------------------------------------------------
__global__ __launch_bounds__(256, 2) void sgemm_bias(
    const float* __restrict__ A, const float* __restrict__ B,
    const float* __restrict__ bias, float* __restrict__ C,
    int M, int N, int K)
{
    __shared__ float As[8][128];
    __shared__ float Bs[8][128];

    const int t  = threadIdx.x;
    const int tx = t & 15;
    const int ty = t >> 4;
    const int m0 = blockIdx.y * 128;
    const int n0 = blockIdx.x * 128;

    const int arow = t >> 1;
    const int acol = (t & 1) << 2;
    const int brow = t >> 5;
    const int bcol = (t & 31) << 2;

    const float* Ap = A + (size_t)(m0 + arow) * K + acol;
    const float* Bp = B + (size_t)brow * N + n0 + bcol;

    float acc[8][8];
#pragma unroll
    for (int i = 0; i < 8; i++)
#pragma unroll
        for (int j = 0; j < 8; j++) acc[i][j] = 0.f;

    float4 av = *(const float4*)Ap;
    float4 bv = *(const float4*)Bp;

    for (int k0 = 0; k0 < K; k0 += 8) {
        As[acol + 0][arow] = av.x;
        As[acol + 1][arow] = av.y;
        As[acol + 2][arow] = av.z;
        As[acol + 3][arow] = av.w;
        *(float4*)(&Bs[brow][bcol]) = bv;
        __syncthreads();

        if (k0 + 8 < K) {
            av = *(const float4*)(Ap + k0 + 8);
            bv = *(const float4*)(Bp + (size_t)(k0 + 8) * N);
        }

#pragma unroll
        for (int kk = 0; kk < 8; kk++) {
            float4 a0 = *(const float4*)(&As[kk][ty * 4]);
            float4 a1 = *(const float4*)(&As[kk][64 + ty * 4]);
            float4 b0 = *(const float4*)(&Bs[kk][tx * 4]);
            float4 b1 = *(const float4*)(&Bs[kk][64 + tx * 4]);
            float a[8] = {a0.x, a0.y, a0.z, a0.w, a1.x, a1.y, a1.z, a1.w};
            float b[8] = {b0.x, b0.y, b0.z, b0.w, b1.x, b1.y, b1.z, b1.w};
#pragma unroll
            for (int i = 0; i < 8; i++)
#pragma unroll
                for (int j = 0; j < 8; j++) acc[i][j] += a[i] * b[j];
        }
        __syncthreads();
    }

    float bb[8];
#pragma unroll
    for (int j = 0; j < 4; j++) {
        bb[j]     = bias[n0 + tx * 4 + j];
        bb[4 + j] = bias[n0 + 64 + tx * 4 + j];
    }

#pragma unroll
    for (int i = 0; i < 8; i++) {
        int row = m0 + ((i < 4) ? (ty * 4 + i) : (64 + ty * 4 + (i - 4)));
        float* Cp = C + (size_t)row * N + n0;
        float4 v0 = make_float4(acc[i][0] + bb[0], acc[i][1] + bb[1],
                                acc[i][2] + bb[2], acc[i][3] + bb[3]);
        float4 v1 = make_float4(acc[i][4] + bb[4], acc[i][5] + bb[5],
                                acc[i][6] + bb[6], acc[i][7] + bb[7]);
        *(float4*)(Cp + tx * 4)      = v0;
        *(float4*)(Cp + 64 + tx * 4) = v1;
    }
}

// ---------------------------------------------------------------------------
// RoPE applied in-place to the Q and K sections of g_qkv.
// ---------------------------------------------------------------------------
__global__ void rope_kernel(float* __restrict__ qkv,
                            const float* __restrict__ cosb,
                            const float* __restrict__ sinb)
{
    int idx = blockIdx.x * blockDim.x + threadIdx.x;   // S*NH*36
    if (idx >= S_TOT * NH * (HD / 2)) return;
    int d   = idx % (HD / 2);
    int tmp = idx / (HD / 2);
    int h   = tmp % NH;
    int s   = tmp / NH;

    float c  = cosb[s * HD + d];
    float sn = sinb[s * HD + d];

    size_t base = (size_t)s * H3 + h * HD + d;

    float q0 = qkv[base], q1 = qkv[base + HD / 2];
    qkv[base]          = q0 * c - q1 * sn;
    qkv[base + HD / 2] = q1 * c + q0 * sn;

    float k0 = qkv[base + HID], k1 = qkv[base + HID + HD / 2];
    qkv[base + HID]          = k0 * c - k1 * sn;
    qkv[base + HID + HD / 2] = k1 * c + k0 * sn;
}

// ---------------------------------------------------------------------------
// Flash attention v2: one block per (seg, head, 64-query tile).
// BQ=64, BKT=64, 256 threads.
// Q and K stored TRANSPOSED (d-major) in smem with a 4-group XOR swizzle so
// the QK inner loop is 2x LDS.128 + 16 FMA per depth (GEMM-like).
// Dynamic smem: 73.5 KB.
// ---------------------------------------------------------------------------
#define BQ  64
#define BK2 64
#define PSTR 68   // sP row stride (16B-aligned, bank-spread)
#define VSTR 73   // sV row stride

// swizzled word index into a [72][64] d-major tile
__device__ __forceinline__ int swz(int d, int r) {
    return d * 64 + ((((r >> 2) ^ d) & 15) << 2) + (r & 3);
}

__global__ __launch_bounds__(256) void attn_kernel(const float* __restrict__ qkv,
                                                   float* __restrict__ ctx)
{
    extern __shared__ float sm[];
    float* sQT = sm;                       // [72][64] swizzled, pre-scaled
    float* sKT = sQT + 72 * 64;            // [72][64] swizzled
    float* sV  = sKT + 72 * 64;            // [64][VSTR]
    float* sP  = sV  + 64 * VSTR;          // [64][PSTR]
    float* sAlpha = sP + 64 * PSTR;        // [64]
    float* sL     = sAlpha + 64;           // [64]

    const int t   = threadIdx.x;
    const int qt  = blockIdx.x;   // 0..15
    const int h   = blockIdx.y;   // 0..15
    const int seg = blockIdx.z;   // 0..7

    const int sbase = seg * LSEG;
    const int qbase = sbase + qt * BQ;

    const int tx = t & 15;        // k-col group (4 cols)
    const int ty = t >> 4;        // q-row group (4 rows)

    // Load Q tile transposed+swizzled, pre-scaled.
    for (int idx = t; idx < BQ * HD; idx += 256) {
        int r = idx / HD, d = idx % HD;
        sQT[swz(d, r)] = qkv[(size_t)(qbase + r) * H3 + h * HD + d] * ATT_SCALE;
    }

    float m_i[4], l_i[4];
#pragma unroll
    for (int i = 0; i < 4; i++) { m_i[i] = -1e30f; l_i[i] = 0.f; }

    // O-phase mapping: 2 rows x 9 cols per thread
    const int orow = (t >> 3) * 2;      // 0,2,...,62
    const int ocol = (t & 7) * 9;       // 0,9,...,63
    float o[2][9];
#pragma unroll
    for (int r = 0; r < 2; r++)
#pragma unroll
        for (int j = 0; j < 9; j++) o[r][j] = 0.f;

    for (int kt = 0; kt < LSEG / BK2; kt++) {
        __syncthreads();   // prev PV done with sV/sP; QK done with sKT
        const int kbase = sbase + kt * BK2;
        for (int idx = t; idx < BK2 * HD; idx += 256) {
            int r = idx / HD, d = idx % HD;
            size_t g = (size_t)(kbase + r) * H3 + h * HD + d;
            sKT[swz(d, r)]    = qkv[g + HID];
            sV[r * VSTR + d]  = qkv[g + 2 * HID];
        }
        __syncthreads();

        // ---- S = Q K^T : per thread 4 q-rows x 4 k-cols ----
        float acc[4][4];
#pragma unroll
        for (int i = 0; i < 4; i++)
#pragma unroll
            for (int j = 0; j < 4; j++) acc[i][j] = 0.f;

#pragma unroll 8
        for (int d = 0; d < HD; d++) {
            float4 a = *(const float4*)(&sQT[d * 64 + (((ty ^ d) & 15) << 2)]);
            float4 b = *(const float4*)(&sKT[d * 64 + (((tx ^ d) & 15) << 2)]);
            float av[4] = {a.x, a.y, a.z, a.w};
            float bv[4] = {b.x, b.y, b.z, b.w};
#pragma unroll
            for (int i = 0; i < 4; i++)
#pragma unroll
                for (int j = 0; j < 4; j++) acc[i][j] += av[i] * bv[j];
        }

        // ---- online softmax (row reduction over 16 tx lanes) ----
#pragma unroll
        for (int i = 0; i < 4; i++) {
            int row = ty * 4 + i;
            float tmax = fmaxf(fmaxf(acc[i][0], acc[i][1]),
                               fmaxf(acc[i][2], acc[i][3]));
#pragma unroll
            for (int off = 8; off >= 1; off >>= 1)
                tmax = fmaxf(tmax, __shfl_xor_sync(0xffffffffu, tmax, off));
            float mnew  = fmaxf(m_i[i], tmax);
            float alpha = __expf(m_i[i] - mnew);
            float p0 = __expf(acc[i][0] - mnew);
            float p1 = __expf(acc[i][1] - mnew);
            float p2 = __expf(acc[i][2] - mnew);
            float p3 = __expf(acc[i][3] - mnew);
            *(float4*)(&sP[row * PSTR + tx * 4]) = make_float4(p0, p1, p2, p3);
            float ps = (p0 + p1) + (p2 + p3);
#pragma unroll
            for (int off = 8; off >= 1; off >>= 1)
                ps += __shfl_xor_sync(0xffffffffu, ps, off);
            l_i[i] = l_i[i] * alpha + ps;
            m_i[i] = mnew;
            if (tx == 0) {
                sAlpha[row] = alpha;
                sL[row]     = l_i[i];
            }
        }
        __syncthreads();

        // ---- O = alpha*O + P @ V ----
        float al0 = sAlpha[orow];
        float al1 = sAlpha[orow + 1];
#pragma unroll
        for (int j = 0; j < 9; j++) { o[0][j] *= al0; o[1][j] *= al1; }
#pragma unroll 4
        for (int k = 0; k < BK2; k++) {
            float p0 = sP[orow * PSTR + k];
            float p1 = sP[(orow + 1) * PSTR + k];
            const float* vr = &sV[k * VSTR + ocol];
#pragma unroll
            for (int j = 0; j < 9; j++) {
                float v = vr[j];
                o[0][j] += p0 * v;
                o[1][j] += p1 * v;
            }
        }
    }

    float inv0 = 1.f / sL[orow];
    float inv1 = 1.f / sL[orow + 1];
    size_t ob0 = (size_t)(qbase + orow) * HID + h * HD + ocol;
#pragma unroll
    for (int j = 0; j < 9; j++) {
        ctx[ob0 + j]       = o[0][j] * inv0;
        ctx[ob0 + HID + j] = o[1][j] * inv1;
    }
}

#define ATTN_SMEM ((72 * 64 * 2 + 64 * VSTR + 64 * PSTR + 128) * (int)sizeof(float))

// ---------------------------------------------------------------------------
// Launch: QKV GEMM -> RoPE -> attention -> out GEMM
// ---------------------------------------------------------------------------
extern "C" void kernel_launch(void* const* d_in, const int* in_sizes, int n_in,
                              void* d_out, int out_size)
{
    const float* hidden = (const float*)d_in[0];   // [1,8192,1152]
    const float* cosb   = (const float*)d_in[1];   // [8192,72]
    const float* sinb   = (const float*)d_in[2];   // [8192,72]
    const float* Wqkv   = (const float*)d_in[3];   // [1152,3456]
    const float* bqkv   = (const float*)d_in[4];   // [3456]
    const float* Wout   = (const float*)d_in[5];   // [1152,1152]
    const float* bout   = (const float*)d_in[6];   // [1152]
    float* out = (float*)d_out;                    // [1,8192,1152] f32

    float *qkv, *ctx;
    cudaGetSymbolAddress((void**)&qkv, g_qkv);
    cudaGetSymbolAddress((void**)&ctx, g_ctx);

    cudaFuncSetAttribute(attn_kernel,
                         cudaFuncAttributeMaxDynamicSharedMemorySize, ATTN_SMEM);

    // 1) QKV projection + bias
    dim3 g1(H3 / 128, S_TOT / 128);
    sgemm_bias<<<g1, 256>>>(hidden, Wqkv, bqkv, qkv, S_TOT, H3, HID);

    // 2) RoPE in-place on Q,K
    int nrope = S_TOT * NH * (HD / 2);
    rope_kernel<<<(nrope + 255) / 256, 256>>>(qkv, cosb, sinb);

    // 3) Segmented attention
    dim3 ga(LSEG / BQ, NH, NSEG);
    attn_kernel<<<ga, 256, ATTN_SMEM>>>(qkv, ctx);

    // 4) Output projection + bias
    dim3 g2(HID / 128, S_TOT / 128);
    sgemm_bias<<<g2, 256>>>(ctx, Wout, bout, out, S_TOT, HID, HID);
}

// round 4
// speedup vs baseline: 1.2684x; 1.2684x over previous
#include <cuda_runtime.h>
#include <cuda_bf16.h>
#include <cstdint>
#include <cstddef>

// Problem constants
#define S_TOT  8192
#define HID    1152
#define NH     16
#define HD     72
#define NSEG   8
#define LSEG   1024
#define H3     3456
#define ATT_SCALE 0.11785113019775793f   // 72^-0.5
#define KP     3456                      // expanded K' = 3*1152 (bf16x3 folded into K)
#define NST    (KP / 32)                 // 108 k-stages of 32

// Scratch (allocation-free rule: __device__ globals)
__device__ float g_qkv[(size_t)S_TOT * H3];              // 113 MB
__device__ float g_ctx[(size_t)S_TOT * HID];             // 37.7 MB
__device__ __nv_bfloat16 g_ap[(size_t)S_TOT * KP];       // A' [M][3K]  56.6 MB
__device__ __nv_bfloat16 g_wqp[(size_t)H3 * KP];         // Wqkv'T [3456][3456]
__device__ __nv_bfloat16 g_wop[(size_t)HID * KP];        // Wout'T [1152][3456]

// ===========================================================================
// PTX helpers (portable: sm_80-class features only — no tcgen05 on compute_103)
// ===========================================================================
__device__ __forceinline__ uint32_t smem_u32(const void* p) {
    uint32_t a;
    asm("{ .reg .u64 t; cvta.to.shared.u64 t, %1; cvt.u32.u64 %0, t; }"
        : "=r"(a) : "l"(p));
    return a;
}
__device__ __forceinline__ void cp_async16(uint32_t s, const void* g) {
    asm volatile("cp.async.cg.shared.global [%0], [%1], 16;" :: "r"(s), "l"(g));
}
#define CP_COMMIT() asm volatile("cp.async.commit_group;" ::: "memory")
#define CP_WAIT0()  asm volatile("cp.async.wait_group 0;" ::: "memory")
#define CP_WAIT1()  asm volatile("cp.async.wait_group 1;" ::: "memory")

__device__ __forceinline__ void ldm_x4(uint32_t addr, uint32_t& r0, uint32_t& r1,
                                       uint32_t& r2, uint32_t& r3) {
    asm volatile("ldmatrix.sync.aligned.m8n8.x4.shared.b16 {%0,%1,%2,%3}, [%4];"
                 : "=r"(r0), "=r"(r1), "=r"(r2), "=r"(r3) : "r"(addr));
}
__device__ __forceinline__ void mma16816(float* c, uint32_t a0, uint32_t a1,
                                         uint32_t a2, uint32_t a3,
                                         uint32_t b0, uint32_t b1) {
    asm volatile(
        "mma.sync.aligned.m16n8k16.row.col.f32.bf16.bf16.f32 "
        "{%0,%1,%2,%3}, {%4,%5,%6,%7}, {%8,%9}, {%0,%1,%2,%3};"
        : "+f"(c[0]), "+f"(c[1]), "+f"(c[2]), "+f"(c[3])
        : "r"(a0), "r"(a1), "r"(a2), "r"(a3), "r"(b0), "r"(b1));
}

// ===========================================================================
// Prep: A' = [Ahi | Alo | Ahi] along K.  Input [M][1152] fp32.
// ===========================================================================
__global__ void split_A3(const float4* __restrict__ X, __nv_bfloat16* __restrict__ ap,
                         int n4)
{
    int i = blockIdx.x * blockDim.x + threadIdx.x;
    if (i >= n4) return;
    int m  = i / (HID / 4);
    int k  = (i % (HID / 4)) * 4;
    float4 x = X[i];
    __nv_bfloat16 h0 = __float2bfloat16(x.x);
    __nv_bfloat16 h1 = __float2bfloat16(x.y);
    __nv_bfloat16 h2 = __float2bfloat16(x.z);
    __nv_bfloat16 h3 = __float2bfloat16(x.w);
    __nv_bfloat16 l0 = __float2bfloat16(x.x - __bfloat162float(h0));
    __nv_bfloat16 l1 = __float2bfloat16(x.y - __bfloat162float(h1));
    __nv_bfloat16 l2 = __float2bfloat16(x.z - __bfloat162float(h2));
    __nv_bfloat16 l3 = __float2bfloat16(x.w - __bfloat162float(h3));
    __nv_bfloat162 hA(h0, h1), hB(h2, h3), lA(l0, l1), lB(l2, l3);
    __nv_bfloat162* p = (__nv_bfloat162*)(ap + (size_t)m * KP + k);
    p[0] = hA; p[1] = hB;                                        // Ahi
    *(__nv_bfloat162*)((__nv_bfloat16*)p + HID)       = lA;      // Alo
    *(__nv_bfloat162*)((__nv_bfloat16*)p + HID + 2)   = lB;
    *(__nv_bfloat162*)((__nv_bfloat16*)p + 2 * HID)     = hA;    // Ahi again
    *(__nv_bfloat162*)((__nv_bfloat16*)p + 2 * HID + 2) = hB;
}

// Prep: B'T = [Bhi | Bhi | Blo] along K, transposed.  W [1152][Nd] fp32 -> [Nd][3456]
__global__ void split_T3(const float* __restrict__ W, __nv_bfloat16* __restrict__ bp,
                         int Nd)
{
    __shared__ float tile[32][33];
    int n0 = blockIdx.x * 32, k0 = blockIdx.y * 32;
    int tx = threadIdx.x, ty = threadIdx.y;   // 32 x 8
    for (int i = ty; i < 32; i += 8)
        tile[i][tx] = W[(size_t)(k0 + i) * Nd + n0 + tx];
    __syncthreads();
    for (int i = ty; i < 32; i += 8) {
        float x = tile[tx][i];                // W[k0+tx][n0+i]
        __nv_bfloat16 h = __float2bfloat16(x);
        __nv_bfloat16 l = __float2bfloat16(x - __bfloat162float(h));
        __nv_bfloat16* row = bp + (size_t)(n0 + i) * KP;
        row[k0 + tx]           = h;           // Bhi
        row[HID + k0 + tx]     = h;           // Bhi
        row[2 * HID + k0 + tx] = l;           // Blo
    }
}

// ===========================================================================
// bf16 mma.sync GEMM: C[M,N] = A'[M,KP] @ B'T[N,KP] + bias[N]
// 128x128 block, 8 warps (warp tile 64x32), BK=32, cp.async double buffer.
// Smem rows strided 80B (40 bf16) -> conflict-free ldmatrix.
// ===========================================================================
#define ASTRIDE 40          // bf16 units per smem row (80 bytes)
#define STAGE_B (128 * 80)  // 10240 bytes per operand stage

__global__ __launch_bounds__(256) void mma_gemm(
    const __nv_bfloat16* __restrict__ Ap, const __nv_bfloat16* __restrict__ Bp,
    const float* __restrict__ bias, float* __restrict__ C, int N)
{
    __shared__ __align__(16) char sm[4 * STAGE_B];   // A0,A1,B0,B1

    const int t    = threadIdx.x;
    const int wid  = t >> 5;
    const int lane = t & 31;
    const int wm   = wid & 1;          // 0..1  (64-row half)
    const int wn   = wid >> 1;         // 0..3  (32-col quarter)
    const int m0   = blockIdx.y * 128;
    const int n0   = blockIdx.x * 128;

    const uint32_t sbase = smem_u32(sm);
    const uint32_t sA[2] = { sbase, sbase + STAGE_B };
    const uint32_t sB[2] = { sbase + 2 * STAGE_B, sbase + 3 * STAGE_B };

    float c[4][4][4];
#pragma unroll
    for (int i = 0; i < 4; i++)
#pragma unroll
        for (int j = 0; j < 4; j++)
#pragma unroll
            for (int q = 0; q < 4; q++) c[i][j][q] = 0.f;

    // stage loader: 128 rows x 32 bf16 (64B) per operand
    auto load_stage = [&](int st, int k0) {
#pragma unroll
        for (int rep = 0; rep < 2; rep++) {
            int cidx = t + rep * 256;              // 0..511
            int row = cidx >> 2;
            int seg = cidx & 3;                    // 16B segment
            uint32_t soff = (uint32_t)(row * 80 + seg * 16);
            cp_async16(sA[st] + soff, Ap + (size_t)(m0 + row) * KP + k0 + seg * 8);
            cp_async16(sB[st] + soff, Bp + (size_t)(n0 + row) * KP + k0 + seg * 8);
        }
    };

    load_stage(0, 0);
    CP_COMMIT();

    const int arow = lane & 15;        // ldmatrix A row within 16
    const int acol = (lane >> 4) * 16; // byte offset of k-half (8 bf16)
    const int bg   = lane >> 3;        // 0..3
    const int brow = lane & 7;
    const int bnt  = bg >> 1;          // n-tile within pair
    const int bkh  = (bg & 1) * 16;    // k-half byte offset

    for (int kt = 0; kt < NST; kt++) {
        const int cur = kt & 1;
        if (kt + 1 < NST) {
            load_stage((kt + 1) & 1, (kt + 1) * 32);
            CP_COMMIT();
            CP_WAIT1();
        } else {
            CP_WAIT0();
        }
        __syncthreads();

#pragma unroll
        for (int kk = 0; kk < 2; kk++) {
            const int kb = kk * 32;    // byte offset of k16 within 64B row
            uint32_t a[4][4];
#pragma unroll
            for (int mt = 0; mt < 4; mt++) {
                uint32_t addr = sA[cur]
                    + (uint32_t)((wm * 64 + mt * 16 + arow) * 80 + kb + acol);
                ldm_x4(addr, a[mt][0], a[mt][1], a[mt][2], a[mt][3]);
            }
            uint32_t b[4][2];
#pragma unroll
            for (int p = 0; p < 2; p++) {
                uint32_t addr = sB[cur]
                    + (uint32_t)((wn * 32 + (p * 2 + bnt) * 8 + brow) * 80 + kb + bkh);
                uint32_t r0, r1, r2, r3;
                ldm_x4(addr, r0, r1, r2, r3);
                b[p * 2][0] = r0; b[p * 2][1] = r1;
                b[p * 2 + 1][0] = r2; b[p * 2 + 1][1] = r3;
            }
#pragma unroll
            for (int mt = 0; mt < 4; mt++)
#pragma unroll
                for (int nt = 0; nt < 4; nt++)
                    mma16816(c[mt][nt], a[mt][0], a[mt][1], a[mt][2], a[mt][3],
                             b[nt][0], b[nt][1]);
        }
        __syncthreads();
    }

    // Epilogue: fragments -> global (+bias)
    const int qrow = lane >> 2;
    const int qcol = (lane & 3) * 2;
#pragma unroll
    for (int nt = 0; nt < 4; nt++) {
        int col = n0 + wn * 32 + nt * 8 + qcol;
        float b0 = bias[col], b1 = bias[col + 1];
#pragma unroll
        for (int mt = 0; mt < 4; mt++) {
            int r0 = m0 + wm * 64 + mt * 16 + qrow;
            float2 v0 = make_float2(c[mt][nt][0] + b0, c[mt][nt][1] + b1);
            float2 v1 = make_float2(c[mt][nt][2] + b0, c[mt][nt][3] + b1);
            *(float2*)(C + (size_t)r0 * N + col)       = v0;
            *(float2*)(C + (size_t)(r0 + 8) * N + col) = v1;
        }
    }
}

// ===========================================================================
// RoPE in-place on Q,K sections of g_qkv
// ===========================================================================
__global__ void rope_kernel(float* __restrict__ qkv,
                            const float* __restrict__ cosb,
                            const float* __restrict__ sinb)
{
    int idx = blockIdx.x * blockDim.x + threadIdx.x;
    if (idx >= S_TOT * NH * (HD / 2)) return;
    int d   = idx % (HD / 2);
    int tmp = idx / (HD / 2);
    int h   = tmp % NH;
    int s   = tmp / NH;

    float c  = cosb[s * HD + d];
    float sn = sinb[s * HD + d];
    size_t base = (size_t)s * H3 + h * HD + d;

    float q0 = qkv[base], q1 = qkv[base + HD / 2];
    qkv[base]          = q0 * c - q1 * sn;
    qkv[base + HD / 2] = q1 * c + q0 * sn;

    float k0 = qkv[base + HID], k1 = qkv[base + HID + HD / 2];
    qkv[base + HID]          = k0 * c - k1 * sn;
    qkv[base + HID + HD / 2] = k1 * c + k0 * sn;
}

// ===========================================================================
// Flash attention (R1 version): BQ=64, BKT=32, 256 threads, static smem
// ===========================================================================
#define BQ 64
#define BKT 32

__global__ __launch_bounds__(256) void attn_kernel(const float* __restrict__ qkv,
                                                   float* __restrict__ ctx)
{
    __shared__ float sQ[BQ][HD + 1];
    __shared__ float sK[BKT][HD + 1];
    __shared__ float sV[BKT][HD + 1];
    __shared__ float sP[BQ][BKT + 1];
    __shared__ float sAlpha[BQ];
    __shared__ float sL[BQ];

    const int t   = threadIdx.x;
    const int qt  = blockIdx.x;
    const int h   = blockIdx.y;
    const int seg = blockIdx.z;

    const int sbase = seg * LSEG;
    const int qbase = sbase + qt * BQ;

    for (int idx = t; idx < BQ * HD; idx += 256) {
        int r = idx / HD, d = idx % HD;
        sQ[r][d] = qkv[(size_t)(qbase + r) * H3 + h * HD + d] * ATT_SCALE;
    }

    const int tx = t & 15;
    const int ty = t >> 4;

    float m_i[4], l_i[4];
#pragma unroll
    for (int i = 0; i < 4; i++) { m_i[i] = -1e30f; l_i[i] = 0.f; }

    const int orow = (t >> 3) * 2;
    const int ocol = (t & 7) * 9;
    float o[2][9];
#pragma unroll
    for (int r = 0; r < 2; r++)
#pragma unroll
        for (int j = 0; j < 9; j++) o[r][j] = 0.f;

    for (int kt = 0; kt < LSEG / BKT; kt++) {
        __syncthreads();
        const int kbase = sbase + kt * BKT;
        for (int idx = t; idx < BKT * HD; idx += 256) {
            int r = idx / HD, d = idx % HD;
            size_t g = (size_t)(kbase + r) * H3 + h * HD + d;
            sK[r][d] = qkv[g + HID];
            sV[r][d] = qkv[g + 2 * HID];
        }
        __syncthreads();

        float acc[4][2] = {{0.f, 0.f}, {0.f, 0.f}, {0.f, 0.f}, {0.f, 0.f}};
#pragma unroll 8
        for (int d = 0; d < HD; d++) {
            float b0 = sK[tx * 2][d];
            float b1 = sK[tx * 2 + 1][d];
#pragma unroll
            for (int i = 0; i < 4; i++) {
                float a = sQ[ty * 4 + i][d];
                acc[i][0] += a * b0;
                acc[i][1] += a * b1;
            }
        }

#pragma unroll
        for (int i = 0; i < 4; i++) {
            float tmax = fmaxf(acc[i][0], acc[i][1]);
#pragma unroll
            for (int off = 8; off >= 1; off >>= 1)
                tmax = fmaxf(tmax, __shfl_xor_sync(0xffffffffu, tmax, off));
            float mnew  = fmaxf(m_i[i], tmax);
            float alpha = __expf(m_i[i] - mnew);
            float p0 = __expf(acc[i][0] - mnew);
            float p1 = __expf(acc[i][1] - mnew);
            sP[ty * 4 + i][tx * 2]     = p0;
            sP[ty * 4 + i][tx * 2 + 1] = p1;
            float ps = p0 + p1;
#pragma unroll
            for (int off = 8; off >= 1; off >>= 1)
                ps += __shfl_xor_sync(0xffffffffu, ps, off);
            l_i[i] = l_i[i] * alpha + ps;
            m_i[i] = mnew;
            if (tx == 0) {
                sAlpha[ty * 4 + i] = alpha;
                sL[ty * 4 + i]     = l_i[i];
            }
        }
        __syncthreads();

        float al0 = sAlpha[orow];
        float al1 = sAlpha[orow + 1];
#pragma unroll
        for (int j = 0; j < 9; j++) { o[0][j] *= al0; o[1][j] *= al1; }
#pragma unroll 4
        for (int k = 0; k < BKT; k++) {
            float p0 = sP[orow][k];
            float p1 = sP[orow + 1][k];
#pragma unroll
            for (int j = 0; j < 9; j++) {
                float v = sV[k][ocol + j];
                o[0][j] += p0 * v;
                o[1][j] += p1 * v;
            }
        }
    }

    float inv0 = 1.f / sL[orow];
    float inv1 = 1.f / sL[orow + 1];
    size_t ob0 = (size_t)(qbase + orow) * HID + h * HD + ocol;
#pragma unroll
    for (int j = 0; j < 9; j++) {
        ctx[ob0 + j]       = o[0][j] * inv0;
        ctx[ob0 + HID + j] = o[1][j] * inv1;
    }
}

// ===========================================================================
// Launch
// ===========================================================================
extern "C" void kernel_launch(void* const* d_in, const int* in_sizes, int n_in,
                              void* d_out, int out_size)
{
    const float* hidden = (const float*)d_in[0];
    const float* cosb   = (const float*)d_in[1];
    const float* sinb   = (const float*)d_in[2];
    const float* Wqkv   = (const float*)d_in[3];
    const float* bqkv   = (const float*)d_in[4];
    const float* Wout   = (const float*)d_in[5];
    const float* bout   = (const float*)d_in[6];
    float* out = (float*)d_out;

    float *qkv, *ctx;
    __nv_bfloat16 *ap, *wqp, *wop;
    cudaGetSymbolAddress((void**)&qkv, g_qkv);
    cudaGetSymbolAddress((void**)&ctx, g_ctx);
    cudaGetSymbolAddress((void**)&ap, g_ap);
    cudaGetSymbolAddress((void**)&wqp, g_wqp);
    cudaGetSymbolAddress((void**)&wop, g_wop);

    int n4 = S_TOT * HID / 4;

    // Prep: expanded bf16x3 operands
    split_A3<<<(n4 + 255) / 256, 256>>>((const float4*)hidden, ap, n4);
    dim3 tb(32, 8);
    split_T3<<<dim3(H3 / 32, HID / 32), tb>>>(Wqkv, wqp, H3);
    split_T3<<<dim3(HID / 32, HID / 32), tb>>>(Wout, wop, HID);

    // 1) QKV projection + bias (tensor cores, bf16x3-in-K)
    mma_gemm<<<dim3(H3 / 128, S_TOT / 128), 256>>>(ap, wqp, bqkv, qkv, H3);

    // 2) RoPE
    int nrope = S_TOT * NH * (HD / 2);
    rope_kernel<<<(nrope + 255) / 256, 256>>>(qkv, cosb, sinb);

    // 3) Attention
    dim3 ga(LSEG / BQ, NH, NSEG);
    attn_kernel<<<ga, 256>>>(qkv, ctx);

    // 4) Output projection + bias
    split_A3<<<(n4 + 255) / 256, 256>>>((const float4*)ctx, ap, n4);
    mma_gemm<<<dim3(HID / 128, S_TOT / 128), 256>>>(ap, wop, bout, out, HID);
}

// round 5
// speedup vs baseline: 2.3128x; 1.8234x over previous
#include <cuda_runtime.h>
#include <cuda_bf16.h>
#include <cuda_fp16.h>
#include <cstdint>
#include <cstddef>

// Problem constants
#define S_TOT  8192
#define HID    1152
#define NH     16
#define HD     72
#define NSEG   8
#define LSEG   1024
#define H3     3456
#define ATT_SCALE 0.11785113019775793f   // 72^-0.5
#define KP     3456                      // expanded K' = 3*1152 (bf16x3 folded into K)
#define NST    (KP / 32)                 // 108 k-stages of 32
#define QKP    224                       // attention Q'/K' depth: 3*72=216 pad to 224

// Scratch (allocation-free rule: __device__ globals)
__device__ float g_qkv[(size_t)S_TOT * H3];              // 113 MB
__device__ float g_ctx[(size_t)S_TOT * HID];             // 37.7 MB
__device__ __nv_bfloat16 g_ap[(size_t)S_TOT * KP];       // A' [M][3K]
__device__ __nv_bfloat16 g_wqp[(size_t)H3 * KP];         // Wqkv'T
__device__ __nv_bfloat16 g_wop[(size_t)HID * KP];        // Wout'T
__device__ __nv_bfloat16 g_qp[(size_t)S_TOT * NH * QKP]; // Q' [s][h][224] (scaled, rope'd)
__device__ __nv_bfloat16 g_kp2[(size_t)S_TOT * NH * QKP];// K' [s][h][224]
__device__ __half        g_vh[(size_t)S_TOT * NH * 80];  // V fp16 [s][h][80] (pad 0)

// ===========================================================================
// PTX helpers (portable sm_80-class only — no tcgen05 on compute_103)
// ===========================================================================
__device__ __forceinline__ uint32_t smem_u32(const void* p) {
    uint32_t a;
    asm("{ .reg .u64 t; cvta.to.shared.u64 t, %1; cvt.u32.u64 %0, t; }"
        : "=r"(a) : "l"(p));
    return a;
}
__device__ __forceinline__ void cp_async16(uint32_t s, const void* g) {
    asm volatile("cp.async.cg.shared.global [%0], [%1], 16;" :: "r"(s), "l"(g));
}
#define CP_COMMIT() asm volatile("cp.async.commit_group;" ::: "memory")
#define CP_WAIT0()  asm volatile("cp.async.wait_group 0;" ::: "memory")
#define CP_WAIT1()  asm volatile("cp.async.wait_group 1;" ::: "memory")

__device__ __forceinline__ void ldm_x4(uint32_t addr, uint32_t& r0, uint32_t& r1,
                                       uint32_t& r2, uint32_t& r3) {
    asm volatile("ldmatrix.sync.aligned.m8n8.x4.shared.b16 {%0,%1,%2,%3}, [%4];"
                 : "=r"(r0), "=r"(r1), "=r"(r2), "=r"(r3) : "r"(addr));
}
__device__ __forceinline__ void ldm_x4_t(uint32_t addr, uint32_t& r0, uint32_t& r1,
                                         uint32_t& r2, uint32_t& r3) {
    asm volatile("ldmatrix.sync.aligned.m8n8.x4.trans.shared.b16 {%0,%1,%2,%3}, [%4];"
                 : "=r"(r0), "=r"(r1), "=r"(r2), "=r"(r3) : "r"(addr));
}
__device__ __forceinline__ void mma16816(float* c, uint32_t a0, uint32_t a1,
                                         uint32_t a2, uint32_t a3,
                                         uint32_t b0, uint32_t b1) {
    asm volatile(
        "mma.sync.aligned.m16n8k16.row.col.f32.bf16.bf16.f32 "
        "{%0,%1,%2,%3}, {%4,%5,%6,%7}, {%8,%9}, {%0,%1,%2,%3};"
        : "+f"(c[0]), "+f"(c[1]), "+f"(c[2]), "+f"(c[3])
        : "r"(a0), "r"(a1), "r"(a2), "r"(a3), "r"(b0), "r"(b1));
}
__device__ __forceinline__ void mma16816h(float* c, uint32_t a0, uint32_t a1,
                                          uint32_t a2, uint32_t a3,
                                          uint32_t b0, uint32_t b1) {
    asm volatile(
        "mma.sync.aligned.m16n8k16.row.col.f32.f16.f16.f32 "
        "{%0,%1,%2,%3}, {%4,%5,%6,%7}, {%8,%9}, {%0,%1,%2,%3};"
        : "+f"(c[0]), "+f"(c[1]), "+f"(c[2]), "+f"(c[3])
        : "r"(a0), "r"(a1), "r"(a2), "r"(a3), "r"(b0), "r"(b1));
}

// ===========================================================================
// Prep: A' = [Ahi | Alo | Ahi] along K.  Input [M][1152] fp32.
// ===========================================================================
__global__ void split_A3(const float4* __restrict__ X, __nv_bfloat16* __restrict__ ap,
                         int n4)
{
    int i = blockIdx.x * blockDim.x + threadIdx.x;
    if (i >= n4) return;
    int m  = i / (HID / 4);
    int k  = (i % (HID / 4)) * 4;
    float4 x = X[i];
    __nv_bfloat16 h0 = __float2bfloat16(x.x);
    __nv_bfloat16 h1 = __float2bfloat16(x.y);
    __nv_bfloat16 h2 = __float2bfloat16(x.z);
    __nv_bfloat16 h3 = __float2bfloat16(x.w);
    __nv_bfloat16 l0 = __float2bfloat16(x.x - __bfloat162float(h0));
    __nv_bfloat16 l1 = __float2bfloat16(x.y - __bfloat162float(h1));
    __nv_bfloat16 l2 = __float2bfloat16(x.z - __bfloat162float(h2));
    __nv_bfloat16 l3 = __float2bfloat16(x.w - __bfloat162float(h3));
    __nv_bfloat162 hA(h0, h1), hB(h2, h3), lA(l0, l1), lB(l2, l3);
    __nv_bfloat162* p = (__nv_bfloat162*)(ap + (size_t)m * KP + k);
    p[0] = hA; p[1] = hB;
    *(__nv_bfloat162*)((__nv_bfloat16*)p + HID)         = lA;
    *(__nv_bfloat162*)((__nv_bfloat16*)p + HID + 2)     = lB;
    *(__nv_bfloat162*)((__nv_bfloat16*)p + 2 * HID)     = hA;
    *(__nv_bfloat162*)((__nv_bfloat16*)p + 2 * HID + 2) = hB;
}

// Prep: B'T = [Bhi | Bhi | Blo] along K, transposed.
__global__ void split_T3(const float* __restrict__ W, __nv_bfloat16* __restrict__ bp,
                         int Nd)
{
    __shared__ float tile[32][33];
    int n0 = blockIdx.x * 32, k0 = blockIdx.y * 32;
    int tx = threadIdx.x, ty = threadIdx.y;   // 32 x 8
    for (int i = ty; i < 32; i += 8)
        tile[i][tx] = W[(size_t)(k0 + i) * Nd + n0 + tx];
    __syncthreads();
    for (int i = ty; i < 32; i += 8) {
        float x = tile[tx][i];
        __nv_bfloat16 h = __float2bfloat16(x);
        __nv_bfloat16 l = __float2bfloat16(x - __bfloat162float(h));
        __nv_bfloat16* row = bp + (size_t)(n0 + i) * KP;
        row[k0 + tx]           = h;
        row[HID + k0 + tx]     = h;
        row[2 * HID + k0 + tx] = l;
    }
}

// ===========================================================================
// bf16 mma.sync GEMM: C[M,N] = A'[M,KP] @ B'T[N,KP] + bias[N]
// ===========================================================================
#define STAGE_B (128 * 80)

__global__ __launch_bounds__(256) void mma_gemm(
    const __nv_bfloat16* __restrict__ Ap, const __nv_bfloat16* __restrict__ Bp,
    const float* __restrict__ bias, float* __restrict__ C, int N)
{
    __shared__ __align__(16) char sm[4 * STAGE_B];

    const int t    = threadIdx.x;
    const int wid  = t >> 5;
    const int lane = t & 31;
    const int wm   = wid & 1;
    const int wn   = wid >> 1;
    const int m0   = blockIdx.y * 128;
    const int n0   = blockIdx.x * 128;

    const uint32_t sbase = smem_u32(sm);
    const uint32_t sA[2] = { sbase, sbase + STAGE_B };
    const uint32_t sB[2] = { sbase + 2 * STAGE_B, sbase + 3 * STAGE_B };

    float c[4][4][4];
#pragma unroll
    for (int i = 0; i < 4; i++)
#pragma unroll
        for (int j = 0; j < 4; j++)
#pragma unroll
            for (int q = 0; q < 4; q++) c[i][j][q] = 0.f;

    auto load_stage = [&](int st, int k0) {
#pragma unroll
        for (int rep = 0; rep < 2; rep++) {
            int cidx = t + rep * 256;
            int row = cidx >> 2;
            int seg = cidx & 3;
            uint32_t soff = (uint32_t)(row * 80 + seg * 16);
            cp_async16(sA[st] + soff, Ap + (size_t)(m0 + row) * KP + k0 + seg * 8);
            cp_async16(sB[st] + soff, Bp + (size_t)(n0 + row) * KP + k0 + seg * 8);
        }
    };

    load_stage(0, 0);
    CP_COMMIT();

    const int arow = lane & 15;
    const int acol = (lane >> 4) * 16;
    const int bg   = lane >> 3;
    const int brow = lane & 7;
    const int bnt  = bg >> 1;
    const int bkh  = (bg & 1) * 16;

    for (int kt = 0; kt < NST; kt++) {
        const int cur = kt & 1;
        if (kt + 1 < NST) {
            load_stage((kt + 1) & 1, (kt + 1) * 32);
            CP_COMMIT();
            CP_WAIT1();
        } else {
            CP_WAIT0();
        }
        __syncthreads();

#pragma unroll
        for (int kk = 0; kk < 2; kk++) {
            const int kb = kk * 32;
            uint32_t a[4][4];
#pragma unroll
            for (int mt = 0; mt < 4; mt++) {
                uint32_t addr = sA[cur]
                    + (uint32_t)((wm * 64 + mt * 16 + arow) * 80 + kb + acol);
                ldm_x4(addr, a[mt][0], a[mt][1], a[mt][2], a[mt][3]);
            }
            uint32_t b[4][2];
#pragma unroll
            for (int p = 0; p < 2; p++) {
                uint32_t addr = sB[cur]
                    + (uint32_t)((wn * 32 + (p * 2 + bnt) * 8 + brow) * 80 + kb + bkh);
                uint32_t r0, r1, r2, r3;
                ldm_x4(addr, r0, r1, r2, r3);
                b[p * 2][0] = r0; b[p * 2][1] = r1;
                b[p * 2 + 1][0] = r2; b[p * 2 + 1][1] = r3;
            }
#pragma unroll
            for (int mt = 0; mt < 4; mt++)
#pragma unroll
                for (int nt = 0; nt < 4; nt++)
                    mma16816(c[mt][nt], a[mt][0], a[mt][1], a[mt][2], a[mt][3],
                             b[nt][0], b[nt][1]);
        }
        __syncthreads();
    }

    const int qrow = lane >> 2;
    const int qcol = (lane & 3) * 2;
#pragma unroll
    for (int nt = 0; nt < 4; nt++) {
        int col = n0 + wn * 32 + nt * 8 + qcol;
        float b0 = bias[col], b1 = bias[col + 1];
#pragma unroll
        for (int mt = 0; mt < 4; mt++) {
            int r0 = m0 + wm * 64 + mt * 16 + qrow;
            float2 v0 = make_float2(c[mt][nt][0] + b0, c[mt][nt][1] + b1);
            float2 v1 = make_float2(c[mt][nt][2] + b0, c[mt][nt][3] + b1);
            *(float2*)(C + (size_t)r0 * N + col)       = v0;
            *(float2*)(C + (size_t)(r0 + 8) * N + col) = v1;
        }
    }
}

// ===========================================================================
// RoPE + split for attention operands:
//   Q' = [hi(q*scale) | lo | hi] bf16 [s][h][224]
//   K' = [hi(k) | hi | lo]       bf16 [s][h][224]
//   V  = fp16 [s][h][80] (dims 72..79 zero)
// ===========================================================================
__global__ void rope_split(const float* __restrict__ qkv,
                           const float* __restrict__ cosb,
                           const float* __restrict__ sinb,
                           __nv_bfloat16* __restrict__ qp,
                           __nv_bfloat16* __restrict__ kp,
                           __half* __restrict__ vh)
{
    int idx = blockIdx.x * blockDim.x + threadIdx.x;
    if (idx >= S_TOT * NH * 36) return;
    int d   = idx % 36;
    int tmp = idx / 36;
    int h   = tmp % NH;
    int s   = tmp / NH;

    float c  = cosb[s * HD + d];
    float sn = sinb[s * HD + d];
    size_t ib = (size_t)s * H3 + h * HD + d;

    float q0 = qkv[ib], q1 = qkv[ib + 36];
    float rq0 = (q0 * c - q1 * sn) * ATT_SCALE;
    float rq1 = (q1 * c + q0 * sn) * ATT_SCALE;
    float k0 = qkv[ib + HID], k1 = qkv[ib + HID + 36];
    float rk0 = k0 * c - k1 * sn;
    float rk1 = k1 * c + k0 * sn;
    float v0 = qkv[ib + 2 * HID], v1 = qkv[ib + 2 * HID + 36];

    size_t ob = ((size_t)s * NH + h) * QKP;
    __nv_bfloat16 hq0 = __float2bfloat16(rq0);
    __nv_bfloat16 hq1 = __float2bfloat16(rq1);
    __nv_bfloat16 lq0 = __float2bfloat16(rq0 - __bfloat162float(hq0));
    __nv_bfloat16 lq1 = __float2bfloat16(rq1 - __bfloat162float(hq1));
    qp[ob + d]            = hq0;
    qp[ob + d + 36]       = hq1;
    qp[ob + 72 + d]       = lq0;
    qp[ob + 72 + d + 36]  = lq1;
    qp[ob + 144 + d]      = hq0;
    qp[ob + 144 + d + 36] = hq1;

    __nv_bfloat16 hk0 = __float2bfloat16(rk0);
    __nv_bfloat16 hk1 = __float2bfloat16(rk1);
    __nv_bfloat16 lk0 = __float2bfloat16(rk0 - __bfloat162float(hk0));
    __nv_bfloat16 lk1 = __float2bfloat16(rk1 - __bfloat162float(hk1));
    kp[ob + d]            = hk0;
    kp[ob + d + 36]       = hk1;
    kp[ob + 72 + d]       = hk0;
    kp[ob + 72 + d + 36]  = hk1;
    kp[ob + 144 + d]      = lk0;
    kp[ob + 144 + d + 36] = lk1;

    size_t vb = ((size_t)s * NH + h) * 80;
    vh[vb + d]      = __float2half(v0);
    vh[vb + d + 36] = __float2half(v1);

    if (d < 8) {
        __nv_bfloat16 z = __float2bfloat16(0.f);
        qp[ob + 216 + d] = z;
        kp[ob + 216 + d] = z;
        vh[vb + 72 + d]  = __float2half(0.f);
    }
}

// ===========================================================================
// FA2-style mma attention: block = (128 queries, head, seg); 8 warps.
// QK^T bf16 (split3 folded in K'=224); softmax in regs; PV fp16.
// Smem: Q' 128x232, K' 2x64x232 (bf16), V 2x64x88 (fp16). 141,312 B.
// ===========================================================================
#define KROW 232          // Q/K smem row stride (bf16 units); 464 B
#define VROW 88           // V  smem row stride (half units); 176 B
#define SQ_BYTES (128 * KROW * 2)
#define SK_BYTES (64 * KROW * 2)
#define SV_BYTES (64 * VROW * 2)
#define ATT_SMEM (SQ_BYTES + 2 * SK_BYTES + 2 * SV_BYTES)

__global__ __launch_bounds__(256, 1) void attn_mma(
    const __nv_bfloat16* __restrict__ Qp, const __nv_bfloat16* __restrict__ Kp,
    const __half* __restrict__ Vh, float* __restrict__ ctx)
{
    extern __shared__ char smA[];
    char* sQ = smA;
    char* sK = smA + SQ_BYTES;
    char* sV = smA + SQ_BYTES + 2 * SK_BYTES;

    const int t    = threadIdx.x;
    const int lane = t & 31;
    const int wid  = t >> 5;
    const int qt   = blockIdx.x;     // 0..7
    const int h    = blockIdx.y;     // 0..15
    const int seg  = blockIdx.z;     // 0..7
    const int sbase = seg * LSEG;
    const int qbase = sbase + qt * 128;
    const int q0    = wid * 16;

    // --- loaders ---
    auto load_q = [&]() {
        for (int c = t; c < 128 * 28; c += 256) {
            int row = c / 28, ch = c % 28;
            cp_async16(smem_u32(sQ + row * 464 + ch * 16),
                       Qp + ((size_t)(qbase + row) * NH + h) * QKP + ch * 8);
        }
    };
    auto load_kv = [&](int st, int kb) {
        char* dk = sK + st * SK_BYTES;
        char* dv = sV + st * SV_BYTES;
        for (int c = t; c < 64 * 28 + 64 * 10; c += 256) {
            if (c < 1792) {
                int row = c / 28, ch = c % 28;
                cp_async16(smem_u32(dk + row * 464 + ch * 16),
                           Kp + ((size_t)(sbase + kb + row) * NH + h) * QKP + ch * 8);
            } else {
                int c2 = c - 1792;
                int row = c2 / 10, ch = c2 % 10;
                cp_async16(smem_u32(dv + row * 176 + ch * 16),
                           Vh + ((size_t)(sbase + kb + row) * NH + h) * 80 + ch * 8);
            }
        }
    };

    load_q(); load_kv(0, 0); CP_COMMIT();
    load_kv(1, 64); CP_COMMIT();

    uint32_t qf[14][4];
    float o[10][4];
#pragma unroll
    for (int j = 0; j < 10; j++)
#pragma unroll
        for (int q = 0; q < 4; q++) o[j][q] = 0.f;
    float m0v = -1e30f, m1v = -1e30f, l0v = 0.f, l1v = 0.f;

    const int qlrow = lane % 16;
    const int qlcol = (lane / 16) * 16;         // bytes
    const int bkey  = (lane / 16) * 8 + (lane % 8);
    const int bkoff = ((lane / 8) & 1) * 16;    // bytes
    const int vkey  = ((lane / 8) & 1) * 8 + (lane % 8);
    const int vdoff = (lane / 16) * 16;         // bytes

    for (int kt = 0; kt < 16; kt++) {
        if (kt == 15) { CP_WAIT0(); } else { CP_WAIT1(); }
        __syncthreads();

        if (kt == 0) {
#pragma unroll
            for (int kk = 0; kk < 14; kk++) {
                uint32_t addr = smem_u32(sQ + (q0 + qlrow) * 464 + kk * 32 + qlcol);
                ldm_x4(addr, qf[kk][0], qf[kk][1], qf[kk][2], qf[kk][3]);
            }
        }

        const char* bk = sK + (kt & 1) * SK_BYTES;
        const char* bv = sV + (kt & 1) * SV_BYTES;

        // ---- S = Q' K'^T : 8 n-tiles (64 keys) ----
        float s[8][4];
#pragma unroll
        for (int j = 0; j < 8; j++)
#pragma unroll
            for (int q = 0; q < 4; q++) s[j][q] = 0.f;

#pragma unroll
        for (int kk = 0; kk < 14; kk++) {
#pragma unroll
            for (int pr = 0; pr < 4; pr++) {
                uint32_t addr = smem_u32(bk + (pr * 16 + bkey) * 464 + kk * 32 + bkoff);
                uint32_t r0, r1, r2, r3;
                ldm_x4(addr, r0, r1, r2, r3);
                mma16816(s[pr * 2],     qf[kk][0], qf[kk][1], qf[kk][2], qf[kk][3], r0, r1);
                mma16816(s[pr * 2 + 1], qf[kk][0], qf[kk][1], qf[kk][2], qf[kk][3], r2, r3);
            }
        }

        // ---- online softmax (rows t/4 and t/4+8; reduce over quad lanes) ----
        float rx0 = -1e30f, rx1 = -1e30f;
#pragma unroll
        for (int j = 0; j < 8; j++) {
            rx0 = fmaxf(rx0, fmaxf(s[j][0], s[j][1]));
            rx1 = fmaxf(rx1, fmaxf(s[j][2], s[j][3]));
        }
        rx0 = fmaxf(rx0, __shfl_xor_sync(0xffffffffu, rx0, 1));
        rx0 = fmaxf(rx0, __shfl_xor_sync(0xffffffffu, rx0, 2));
        rx1 = fmaxf(rx1, __shfl_xor_sync(0xffffffffu, rx1, 1));
        rx1 = fmaxf(rx1, __shfl_xor_sync(0xffffffffu, rx1, 2));

        float mn0 = fmaxf(m0v, rx0), mn1 = fmaxf(m1v, rx1);
        float a0 = __expf(m0v - mn0), a1 = __expf(m1v - mn1);
        m0v = mn0; m1v = mn1;

        float sum0 = 0.f, sum1 = 0.f;
#pragma unroll
        for (int j = 0; j < 8; j++) {
            s[j][0] = __expf(s[j][0] - mn0);
            s[j][1] = __expf(s[j][1] - mn0);
            s[j][2] = __expf(s[j][2] - mn1);
            s[j][3] = __expf(s[j][3] - mn1);
            sum0 += s[j][0] + s[j][1];
            sum1 += s[j][2] + s[j][3];
        }
        sum0 += __shfl_xor_sync(0xffffffffu, sum0, 1);
        sum0 += __shfl_xor_sync(0xffffffffu, sum0, 2);
        sum1 += __shfl_xor_sync(0xffffffffu, sum1, 1);
        sum1 += __shfl_xor_sync(0xffffffffu, sum1, 2);
        l0v = l0v * a0 + sum0;
        l1v = l1v * a1 + sum1;

#pragma unroll
        for (int j = 0; j < 10; j++) {
            o[j][0] *= a0; o[j][1] *= a0;
            o[j][2] *= a1; o[j][3] *= a1;
        }

        // pack P into fp16 A fragments
        uint32_t pa[4][4];
#pragma unroll
        for (int kk2 = 0; kk2 < 4; kk2++) {
            int j = 2 * kk2;
            __half2 h0 = __floats2half2_rn(s[j][0],     s[j][1]);
            __half2 h1 = __floats2half2_rn(s[j][2],     s[j][3]);
            __half2 h2 = __floats2half2_rn(s[j + 1][0], s[j + 1][1]);
            __half2 h3 = __floats2half2_rn(s[j + 1][2], s[j + 1][3]);
            pa[kk2][0] = *(uint32_t*)&h0;
            pa[kk2][1] = *(uint32_t*)&h1;
            pa[kk2][2] = *(uint32_t*)&h2;
            pa[kk2][3] = *(uint32_t*)&h3;
        }

        // ---- O += P V : 10 n-tiles (80 dims), 4 k16 steps ----
#pragma unroll
        for (int kk2 = 0; kk2 < 4; kk2++) {
#pragma unroll
            for (int vp = 0; vp < 5; vp++) {
                uint32_t addr = smem_u32(bv + (kk2 * 16 + vkey) * 176 + vp * 32 + vdoff);
                uint32_t r0, r1, r2, r3;
                ldm_x4_t(addr, r0, r1, r2, r3);
                mma16816h(o[vp * 2],     pa[kk2][0], pa[kk2][1], pa[kk2][2], pa[kk2][3], r0, r1);
                mma16816h(o[vp * 2 + 1], pa[kk2][0], pa[kk2][1], pa[kk2][2], pa[kk2][3], r2, r3);
            }
        }

        __syncthreads();
        if (kt + 2 < 16) {
            load_kv(kt & 1, (kt + 2) * 64);
            CP_COMMIT();
        }
    }

    // ---- store (dims 0..71 only) ----
    float inv0 = 1.f / l0v, inv1 = 1.f / l1v;
    int r_lo = qbase + q0 + lane / 4;
    int r_hi = r_lo + 8;
#pragma unroll
    for (int j = 0; j < 9; j++) {
        int d = h * HD + j * 8 + (lane & 3) * 2;
        *(float2*)(ctx + (size_t)r_lo * HID + d) = make_float2(o[j][0] * inv0, o[j][1] * inv0);
        *(float2*)(ctx + (size_t)r_hi * HID + d) = make_float2(o[j][2] * inv1, o[j][3] * inv1);
    }
}

// ===========================================================================
// Launch
// ===========================================================================
extern "C" void kernel_launch(void* const* d_in, const int* in_sizes, int n_in,
                              void* d_out, int out_size)
{
    const float* hidden = (const float*)d_in[0];
    const float* cosb   = (const float*)d_in[1];
    const float* sinb   = (const float*)d_in[2];
    const float* Wqkv   = (const float*)d_in[3];
    const float* bqkv   = (const float*)d_in[4];
    const float* Wout   = (const float*)d_in[5];
    const float* bout   = (const float*)d_in[6];
    float* out = (float*)d_out;

    float *qkv, *ctx;
    __nv_bfloat16 *ap, *wqp, *wop, *qp, *kp2;
    __half *vh;
    cudaGetSymbolAddress((void**)&qkv, g_qkv);
    cudaGetSymbolAddress((void**)&ctx, g_ctx);
    cudaGetSymbolAddress((void**)&ap, g_ap);
    cudaGetSymbolAddress((void**)&wqp, g_wqp);
    cudaGetSymbolAddress((void**)&wop, g_wop);
    cudaGetSymbolAddress((void**)&qp, g_qp);
    cudaGetSymbolAddress((void**)&kp2, g_kp2);
    cudaGetSymbolAddress((void**)&vh, g_vh);

    cudaFuncSetAttribute(attn_mma, cudaFuncAttributeMaxDynamicSharedMemorySize, ATT_SMEM);

    int n4 = S_TOT * HID / 4;

    // Prep: expanded bf16x3 operands
    split_A3<<<(n4 + 255) / 256, 256>>>((const float4*)hidden, ap, n4);
    dim3 tb(32, 8);
    split_T3<<<dim3(H3 / 32, HID / 32), tb>>>(Wqkv, wqp, H3);
    split_T3<<<dim3(HID / 32, HID / 32), tb>>>(Wout, wop, HID);

    // 1) QKV projection + bias (tensor cores)
    mma_gemm<<<dim3(H3 / 128, S_TOT / 128), 256>>>(ap, wqp, bqkv, qkv, H3);

    // 2) RoPE + attention-operand split
    int nrope = S_TOT * NH * 36;
    rope_split<<<(nrope + 255) / 256, 256>>>(qkv, cosb, sinb, qp, kp2, vh);

    // 3) Attention (tensor cores)
    dim3 ga(8, NH, NSEG);
    attn_mma<<<ga, 256, ATT_SMEM>>>(qp, kp2, vh, ctx);

    // 4) Output projection + bias (tensor cores)
    split_A3<<<(n4 + 255) / 256, 256>>>((const float4*)ctx, ap, n4);
    mma_gemm<<<dim3(HID / 128, S_TOT / 128), 256>>>(ap, wop, bout, out, HID);
}

// round 6
// speedup vs baseline: 2.4924x; 1.0776x over previous
#include <cuda_runtime.h>
#include <cuda_bf16.h>
#include <cuda_fp16.h>
#include <cstdint>
#include <cstddef>

// Problem constants
#define S_TOT  8192
#define HID    1152
#define NH     16
#define HD     72
#define NSEG   8
#define LSEG   1024
#define H3     3456
#define ATT_SCALE 0.11785113019775793f   // 72^-0.5
#define KP     3456                      // expanded K' = 3*1152 (bf16x3 folded into K)
#define NST    (KP / 32)                 // 108 k-stages of 32
#define QKP    224                       // attention Q'/K' depth: 3*72=216 pad to 224

// Scratch (allocation-free rule: __device__ globals)
__device__ float g_qkv[(size_t)S_TOT * H3];              // 113 MB
__device__ __nv_bfloat16 g_ap[(size_t)S_TOT * KP];       // A' [M][3K]
__device__ __nv_bfloat16 g_wqp[(size_t)H3 * KP];         // Wqkv'T
__device__ __nv_bfloat16 g_wop[(size_t)HID * KP];        // Wout'T
__device__ __nv_bfloat16 g_qp[(size_t)S_TOT * NH * QKP]; // Q' [s][h][224]
__device__ __nv_bfloat16 g_kp2[(size_t)S_TOT * NH * QKP];// K' [s][h][224]
__device__ __half        g_vh[(size_t)S_TOT * NH * 80];  // V fp16 [s][h][80]

// ===========================================================================
// PTX helpers (portable sm_80-class only — no tcgen05 on compute_103)
// ===========================================================================
__device__ __forceinline__ uint32_t smem_u32(const void* p) {
    uint32_t a;
    asm("{ .reg .u64 t; cvta.to.shared.u64 t, %1; cvt.u32.u64 %0, t; }"
        : "=r"(a) : "l"(p));
    return a;
}
__device__ __forceinline__ void cp_async16(uint32_t s, const void* g) {
    asm volatile("cp.async.cg.shared.global [%0], [%1], 16;" :: "r"(s), "l"(g));
}
#define CP_COMMIT() asm volatile("cp.async.commit_group;" ::: "memory")
#define CP_WAIT0()  asm volatile("cp.async.wait_group 0;" ::: "memory")
#define CP_WAIT1()  asm volatile("cp.async.wait_group 1;" ::: "memory")
#define CP_WAIT2()  asm volatile("cp.async.wait_group 2;" ::: "memory")

__device__ __forceinline__ void ldm_x4(uint32_t addr, uint32_t& r0, uint32_t& r1,
                                       uint32_t& r2, uint32_t& r3) {
    asm volatile("ldmatrix.sync.aligned.m8n8.x4.shared.b16 {%0,%1,%2,%3}, [%4];"
                 : "=r"(r0), "=r"(r1), "=r"(r2), "=r"(r3) : "r"(addr));
}
__device__ __forceinline__ void ldm_x4_t(uint32_t addr, uint32_t& r0, uint32_t& r1,
                                         uint32_t& r2, uint32_t& r3) {
    asm volatile("ldmatrix.sync.aligned.m8n8.x4.trans.shared.b16 {%0,%1,%2,%3}, [%4];"
                 : "=r"(r0), "=r"(r1), "=r"(r2), "=r"(r3) : "r"(addr));
}
__device__ __forceinline__ void mma16816(float* c, uint32_t a0, uint32_t a1,
                                         uint32_t a2, uint32_t a3,
                                         uint32_t b0, uint32_t b1) {
    asm volatile(
        "mma.sync.aligned.m16n8k16.row.col.f32.bf16.bf16.f32 "
        "{%0,%1,%2,%3}, {%4,%5,%6,%7}, {%8,%9}, {%0,%1,%2,%3};"
        : "+f"(c[0]), "+f"(c[1]), "+f"(c[2]), "+f"(c[3])
        : "r"(a0), "r"(a1), "r"(a2), "r"(a3), "r"(b0), "r"(b1));
}
__device__ __forceinline__ void mma16816h(float* c, uint32_t a0, uint32_t a1,
                                          uint32_t a2, uint32_t a3,
                                          uint32_t b0, uint32_t b1) {
    asm volatile(
        "mma.sync.aligned.m16n8k16.row.col.f32.f16.f16.f32 "
        "{%0,%1,%2,%3}, {%4,%5,%6,%7}, {%8,%9}, {%0,%1,%2,%3};"
        : "+f"(c[0]), "+f"(c[1]), "+f"(c[2]), "+f"(c[3])
        : "r"(a0), "r"(a1), "r"(a2), "r"(a3), "r"(b0), "r"(b1));
}

// ===========================================================================
// Prep: A' = [Ahi | Alo | Ahi] along K.  Input [M][1152] fp32.
// ===========================================================================
__global__ void split_A3(const float4* __restrict__ X, __nv_bfloat16* __restrict__ ap,
                         int n4)
{
    int i = blockIdx.x * blockDim.x + threadIdx.x;
    if (i >= n4) return;
    int m  = i / (HID / 4);
    int k  = (i % (HID / 4)) * 4;
    float4 x = X[i];
    __nv_bfloat16 h0 = __float2bfloat16(x.x);
    __nv_bfloat16 h1 = __float2bfloat16(x.y);
    __nv_bfloat16 h2 = __float2bfloat16(x.z);
    __nv_bfloat16 h3 = __float2bfloat16(x.w);
    __nv_bfloat16 l0 = __float2bfloat16(x.x - __bfloat162float(h0));
    __nv_bfloat16 l1 = __float2bfloat16(x.y - __bfloat162float(h1));
    __nv_bfloat16 l2 = __float2bfloat16(x.z - __bfloat162float(h2));
    __nv_bfloat16 l3 = __float2bfloat16(x.w - __bfloat162float(h3));
    __nv_bfloat162 hA(h0, h1), hB(h2, h3), lA(l0, l1), lB(l2, l3);
    __nv_bfloat162* p = (__nv_bfloat162*)(ap + (size_t)m * KP + k);
    p[0] = hA; p[1] = hB;
    *(__nv_bfloat162*)((__nv_bfloat16*)p + HID)         = lA;
    *(__nv_bfloat162*)((__nv_bfloat16*)p + HID + 2)     = lB;
    *(__nv_bfloat162*)((__nv_bfloat16*)p + 2 * HID)     = hA;
    *(__nv_bfloat162*)((__nv_bfloat16*)p + 2 * HID + 2) = hB;
}

// Prep: B'T = [Bhi | Bhi | Blo] along K, transposed.
__global__ void split_T3(const float* __restrict__ W, __nv_bfloat16* __restrict__ bp,
                         int Nd)
{
    __shared__ float tile[32][33];
    int n0 = blockIdx.x * 32, k0 = blockIdx.y * 32;
    int tx = threadIdx.x, ty = threadIdx.y;   // 32 x 8
    for (int i = ty; i < 32; i += 8)
        tile[i][tx] = W[(size_t)(k0 + i) * Nd + n0 + tx];
    __syncthreads();
    for (int i = ty; i < 32; i += 8) {
        float x = tile[tx][i];
        __nv_bfloat16 h = __float2bfloat16(x);
        __nv_bfloat16 l = __float2bfloat16(x - __bfloat162float(h));
        __nv_bfloat16* row = bp + (size_t)(n0 + i) * KP;
        row[k0 + tx]           = h;
        row[HID + k0 + tx]     = h;
        row[2 * HID + k0 + tx] = l;
    }
}

// ===========================================================================
// bf16 mma.sync GEMM: C[M,N] = A'[M,KP] @ B'T[N,KP] + bias[N]
// 128x128 block, 8 warps (64x32 each), BK=32, 4-stage cp.async ring,
// ONE __syncthreads per stage.
// ===========================================================================
#define STAGE_B 20480                 // A (10240) + B (10240) per stage
#define GEMM_SMEM (4 * STAGE_B)       // 81,920 B

__global__ __launch_bounds__(256) void mma_gemm(
    const __nv_bfloat16* __restrict__ Ap, const __nv_bfloat16* __restrict__ Bp,
    const float* __restrict__ bias, float* __restrict__ C, int N)
{
    extern __shared__ __align__(16) char sm[];

    const int t    = threadIdx.x;
    const int wid  = t >> 5;
    const int lane = t & 31;
    const int wm   = wid & 1;
    const int wn   = wid >> 1;
    const int m0   = blockIdx.y * 128;
    const int n0   = blockIdx.x * 128;

    const uint32_t sbase = smem_u32(sm);

    float c[4][4][4];
#pragma unroll
    for (int i = 0; i < 4; i++)
#pragma unroll
        for (int j = 0; j < 4; j++)
#pragma unroll
            for (int q = 0; q < 4; q++) c[i][j][q] = 0.f;

    // one stage: A 128 rows x 32 bf16 (80B-strided rows), B likewise at +10240
    auto load_stage = [&](int st, int k0) {
        uint32_t sA = sbase + st * STAGE_B;
        uint32_t sB = sA + 10240;
#pragma unroll
        for (int rep = 0; rep < 2; rep++) {
            int cidx = t + rep * 256;
            int row = cidx >> 2;
            int seg = cidx & 3;
            uint32_t soff = (uint32_t)(row * 80 + seg * 16);
            cp_async16(sA + soff, Ap + (size_t)(m0 + row) * KP + k0 + seg * 8);
            cp_async16(sB + soff, Bp + (size_t)(n0 + row) * KP + k0 + seg * 8);
        }
    };

    load_stage(0, 0);  CP_COMMIT();
    load_stage(1, 32); CP_COMMIT();
    load_stage(2, 64); CP_COMMIT();

    const int arow = lane & 15;
    const int acol = (lane >> 4) * 16;
    const int bg   = lane >> 3;
    const int brow = lane & 7;
    const int bnt  = bg >> 1;
    const int bkh  = (bg & 1) * 16;

    for (int kt = 0; kt < NST; kt++) {
        CP_WAIT2();                 // stage kt complete (2 newer groups may pend)
        __syncthreads();            // visibility + all warps done with stage kt-1

        if (kt + 3 < NST) load_stage((kt + 3) & 3, (kt + 3) * 32);
        CP_COMMIT();                // always commit (keeps group count constant)

        const uint32_t sA = sbase + (kt & 3) * STAGE_B;
        const uint32_t sB = sA + 10240;

#pragma unroll
        for (int kk = 0; kk < 2; kk++) {
            const int kb = kk * 32;
            uint32_t a[4][4];
#pragma unroll
            for (int mt = 0; mt < 4; mt++) {
                uint32_t addr = sA
                    + (uint32_t)((wm * 64 + mt * 16 + arow) * 80 + kb + acol);
                ldm_x4(addr, a[mt][0], a[mt][1], a[mt][2], a[mt][3]);
            }
            uint32_t b[4][2];
#pragma unroll
            for (int p = 0; p < 2; p++) {
                uint32_t addr = sB
                    + (uint32_t)((wn * 32 + (p * 2 + bnt) * 8 + brow) * 80 + kb + bkh);
                uint32_t r0, r1, r2, r3;
                ldm_x4(addr, r0, r1, r2, r3);
                b[p * 2][0] = r0; b[p * 2][1] = r1;
                b[p * 2 + 1][0] = r2; b[p * 2 + 1][1] = r3;
            }
#pragma unroll
            for (int mt = 0; mt < 4; mt++)
#pragma unroll
                for (int nt = 0; nt < 4; nt++)
                    mma16816(c[mt][nt], a[mt][0], a[mt][1], a[mt][2], a[mt][3],
                             b[nt][0], b[nt][1]);
        }
    }

    const int qrow = lane >> 2;
    const int qcol = (lane & 3) * 2;
#pragma unroll
    for (int nt = 0; nt < 4; nt++) {
        int col = n0 + wn * 32 + nt * 8 + qcol;
        float b0 = bias[col], b1 = bias[col + 1];
#pragma unroll
        for (int mt = 0; mt < 4; mt++) {
            int r0 = m0 + wm * 64 + mt * 16 + qrow;
            float2 v0 = make_float2(c[mt][nt][0] + b0, c[mt][nt][1] + b1);
            float2 v1 = make_float2(c[mt][nt][2] + b0, c[mt][nt][3] + b1);
            *(float2*)(C + (size_t)r0 * N + col)       = v0;
            *(float2*)(C + (size_t)(r0 + 8) * N + col) = v1;
        }
    }
}

// ===========================================================================
// RoPE + split for attention operands (Q'/K' bf16x3, V fp16)
// ===========================================================================
__global__ void rope_split(const float* __restrict__ qkv,
                           const float* __restrict__ cosb,
                           const float* __restrict__ sinb,
                           __nv_bfloat16* __restrict__ qp,
                           __nv_bfloat16* __restrict__ kp,
                           __half* __restrict__ vh)
{
    int idx = blockIdx.x * blockDim.x + threadIdx.x;
    if (idx >= S_TOT * NH * 36) return;
    int d   = idx % 36;
    int tmp = idx / 36;
    int h   = tmp % NH;
    int s   = tmp / NH;

    float c  = cosb[s * HD + d];
    float sn = sinb[s * HD + d];
    size_t ib = (size_t)s * H3 + h * HD + d;

    float q0 = qkv[ib], q1 = qkv[ib + 36];
    float rq0 = (q0 * c - q1 * sn) * ATT_SCALE;
    float rq1 = (q1 * c + q0 * sn) * ATT_SCALE;
    float k0 = qkv[ib + HID], k1 = qkv[ib + HID + 36];
    float rk0 = k0 * c - k1 * sn;
    float rk1 = k1 * c + k0 * sn;
    float v0 = qkv[ib + 2 * HID], v1 = qkv[ib + 2 * HID + 36];

    size_t ob = ((size_t)s * NH + h) * QKP;
    __nv_bfloat16 hq0 = __float2bfloat16(rq0);
    __nv_bfloat16 hq1 = __float2bfloat16(rq1);
    __nv_bfloat16 lq0 = __float2bfloat16(rq0 - __bfloat162float(hq0));
    __nv_bfloat16 lq1 = __float2bfloat16(rq1 - __bfloat162float(hq1));
    qp[ob + d]            = hq0;
    qp[ob + d + 36]       = hq1;
    qp[ob + 72 + d]       = lq0;
    qp[ob + 72 + d + 36]  = lq1;
    qp[ob + 144 + d]      = hq0;
    qp[ob + 144 + d + 36] = hq1;

    __nv_bfloat16 hk0 = __float2bfloat16(rk0);
    __nv_bfloat16 hk1 = __float2bfloat16(rk1);
    __nv_bfloat16 lk0 = __float2bfloat16(rk0 - __bfloat162float(hk0));
    __nv_bfloat16 lk1 = __float2bfloat16(rk1 - __bfloat162float(hk1));
    kp[ob + d]            = hk0;
    kp[ob + d + 36]       = hk1;
    kp[ob + 72 + d]       = hk0;
    kp[ob + 72 + d + 36]  = hk1;
    kp[ob + 144 + d]      = lk0;
    kp[ob + 144 + d + 36] = lk1;

    size_t vb = ((size_t)s * NH + h) * 80;
    vh[vb + d]      = __float2half(v0);
    vh[vb + d + 36] = __float2half(v1);

    if (d < 8) {
        __nv_bfloat16 z = __float2bfloat16(0.f);
        qp[ob + 216 + d] = z;
        kp[ob + 216 + d] = z;
        vh[vb + 72 + d]  = __float2half(0.f);
    }
}

// ===========================================================================
// FA2-style mma attention; epilogue writes bf16x3 split DIRECTLY into g_ap
// (input of the out-projection), removing the fp32 ctx round-trip.
// ===========================================================================
#define SQ_BYTES (128 * 464)
#define SK_BYTES (64 * 464)
#define SV_BYTES (64 * 176)
#define ATT_SMEM (SQ_BYTES + 2 * SK_BYTES + 2 * SV_BYTES)

__global__ __launch_bounds__(256, 1) void attn_mma(
    const __nv_bfloat16* __restrict__ Qp, const __nv_bfloat16* __restrict__ Kp,
    const __half* __restrict__ Vh, __nv_bfloat16* __restrict__ ap)
{
    extern __shared__ char smA[];
    char* sQ = smA;
    char* sK = smA + SQ_BYTES;
    char* sV = smA + SQ_BYTES + 2 * SK_BYTES;

    const int t    = threadIdx.x;
    const int lane = t & 31;
    const int wid  = t >> 5;
    const int qt   = blockIdx.x;     // 0..7
    const int h    = blockIdx.y;     // 0..15
    const int seg  = blockIdx.z;     // 0..7
    const int sbase = seg * LSEG;
    const int qbase = sbase + qt * 128;
    const int q0    = wid * 16;

    auto load_q = [&]() {
        for (int c = t; c < 128 * 28; c += 256) {
            int row = c / 28, ch = c % 28;
            cp_async16(smem_u32(sQ + row * 464 + ch * 16),
                       Qp + ((size_t)(qbase + row) * NH + h) * QKP + ch * 8);
        }
    };
    auto load_kv = [&](int st, int kb) {
        char* dk = sK + st * SK_BYTES;
        char* dv = sV + st * SV_BYTES;
        for (int c = t; c < 64 * 28 + 64 * 10; c += 256) {
            if (c < 1792) {
                int row = c / 28, ch = c % 28;
                cp_async16(smem_u32(dk + row * 464 + ch * 16),
                           Kp + ((size_t)(sbase + kb + row) * NH + h) * QKP + ch * 8);
            } else {
                int c2 = c - 1792;
                int row = c2 / 10, ch = c2 % 10;
                cp_async16(smem_u32(dv + row * 176 + ch * 16),
                           Vh + ((size_t)(sbase + kb + row) * NH + h) * 80 + ch * 8);
            }
        }
    };

    load_q(); load_kv(0, 0); CP_COMMIT();
    load_kv(1, 64); CP_COMMIT();

    uint32_t qf[14][4];
    float o[10][4];
#pragma unroll
    for (int j = 0; j < 10; j++)
#pragma unroll
        for (int q = 0; q < 4; q++) o[j][q] = 0.f;
    float m0v = -1e30f, m1v = -1e30f, l0v = 0.f, l1v = 0.f;

    const int qlrow = lane % 16;
    const int qlcol = (lane / 16) * 16;
    const int bkey  = (lane / 16) * 8 + (lane % 8);
    const int bkoff = ((lane / 8) & 1) * 16;
    const int vkey  = ((lane / 8) & 1) * 8 + (lane % 8);
    const int vdoff = (lane / 16) * 16;

    for (int kt = 0; kt < 16; kt++) {
        if (kt == 15) { CP_WAIT0(); } else { CP_WAIT1(); }
        __syncthreads();

        if (kt == 0) {
#pragma unroll
            for (int kk = 0; kk < 14; kk++) {
                uint32_t addr = smem_u32(sQ + (q0 + qlrow) * 464 + kk * 32 + qlcol);
                ldm_x4(addr, qf[kk][0], qf[kk][1], qf[kk][2], qf[kk][3]);
            }
        }

        const char* bk = sK + (kt & 1) * SK_BYTES;
        const char* bv = sV + (kt & 1) * SV_BYTES;

        float s[8][4];
#pragma unroll
        for (int j = 0; j < 8; j++)
#pragma unroll
            for (int q = 0; q < 4; q++) s[j][q] = 0.f;

#pragma unroll
        for (int kk = 0; kk < 14; kk++) {
#pragma unroll
            for (int pr = 0; pr < 4; pr++) {
                uint32_t addr = smem_u32(bk + (pr * 16 + bkey) * 464 + kk * 32 + bkoff);
                uint32_t r0, r1, r2, r3;
                ldm_x4(addr, r0, r1, r2, r3);
                mma16816(s[pr * 2],     qf[kk][0], qf[kk][1], qf[kk][2], qf[kk][3], r0, r1);
                mma16816(s[pr * 2 + 1], qf[kk][0], qf[kk][1], qf[kk][2], qf[kk][3], r2, r3);
            }
        }

        float rx0 = -1e30f, rx1 = -1e30f;
#pragma unroll
        for (int j = 0; j < 8; j++) {
            rx0 = fmaxf(rx0, fmaxf(s[j][0], s[j][1]));
            rx1 = fmaxf(rx1, fmaxf(s[j][2], s[j][3]));
        }
        rx0 = fmaxf(rx0, __shfl_xor_sync(0xffffffffu, rx0, 1));
        rx0 = fmaxf(rx0, __shfl_xor_sync(0xffffffffu, rx0, 2));
        rx1 = fmaxf(rx1, __shfl_xor_sync(0xffffffffu, rx1, 1));
        rx1 = fmaxf(rx1, __shfl_xor_sync(0xffffffffu, rx1, 2));

        float mn0 = fmaxf(m0v, rx0), mn1 = fmaxf(m1v, rx1);
        float a0 = __expf(m0v - mn0), a1 = __expf(m1v - mn1);
        m0v = mn0; m1v = mn1;

        float sum0 = 0.f, sum1 = 0.f;
#pragma unroll
        for (int j = 0; j < 8; j++) {
            s[j][0] = __expf(s[j][0] - mn0);
            s[j][1] = __expf(s[j][1] - mn0);
            s[j][2] = __expf(s[j][2] - mn1);
            s[j][3] = __expf(s[j][3] - mn1);
            sum0 += s[j][0] + s[j][1];
            sum1 += s[j][2] + s[j][3];
        }
        sum0 += __shfl_xor_sync(0xffffffffu, sum0, 1);
        sum0 += __shfl_xor_sync(0xffffffffu, sum0, 2);
        sum1 += __shfl_xor_sync(0xffffffffu, sum1, 1);
        sum1 += __shfl_xor_sync(0xffffffffu, sum1, 2);
        l0v = l0v * a0 + sum0;
        l1v = l1v * a1 + sum1;

#pragma unroll
        for (int j = 0; j < 10; j++) {
            o[j][0] *= a0; o[j][1] *= a0;
            o[j][2] *= a1; o[j][3] *= a1;
        }

        uint32_t pa[4][4];
#pragma unroll
        for (int kk2 = 0; kk2 < 4; kk2++) {
            int j = 2 * kk2;
            __half2 h0 = __floats2half2_rn(s[j][0],     s[j][1]);
            __half2 h1 = __floats2half2_rn(s[j][2],     s[j][3]);
            __half2 h2 = __floats2half2_rn(s[j + 1][0], s[j + 1][1]);
            __half2 h3 = __floats2half2_rn(s[j + 1][2], s[j + 1][3]);
            pa[kk2][0] = *(uint32_t*)&h0;
            pa[kk2][1] = *(uint32_t*)&h1;
            pa[kk2][2] = *(uint32_t*)&h2;
            pa[kk2][3] = *(uint32_t*)&h3;
        }

#pragma unroll
        for (int kk2 = 0; kk2 < 4; kk2++) {
#pragma unroll
            for (int vp = 0; vp < 5; vp++) {
                uint32_t addr = smem_u32(bv + (kk2 * 16 + vkey) * 176 + vp * 32 + vdoff);
                uint32_t r0, r1, r2, r3;
                ldm_x4_t(addr, r0, r1, r2, r3);
                mma16816h(o[vp * 2],     pa[kk2][0], pa[kk2][1], pa[kk2][2], pa[kk2][3], r0, r1);
                mma16816h(o[vp * 2 + 1], pa[kk2][0], pa[kk2][1], pa[kk2][2], pa[kk2][3], r2, r3);
            }
        }

        __syncthreads();
        if (kt + 2 < 16) {
            load_kv(kt & 1, (kt + 2) * 64);
            CP_COMMIT();
        }
    }

    // ---- store bf16x3 split directly into A' rows (dims 0..71 only) ----
    float inv0 = 1.f / l0v, inv1 = 1.f / l1v;
    int r_lo = qbase + q0 + lane / 4;
    int r_hi = r_lo + 8;
#pragma unroll
    for (int j = 0; j < 9; j++) {
        int col = h * HD + j * 8 + (lane & 3) * 2;
        float x0 = o[j][0] * inv0, x1 = o[j][1] * inv0;
        float x2 = o[j][2] * inv1, x3 = o[j][3] * inv1;

        __nv_bfloat16 hx0 = __float2bfloat16(x0);
        __nv_bfloat16 hx1 = __float2bfloat16(x1);
        __nv_bfloat162 hp0(hx0, hx1);
        __nv_bfloat162 lp0(__float2bfloat16(x0 - __bfloat162float(hx0)),
                           __float2bfloat16(x1 - __bfloat162float(hx1)));
        __nv_bfloat16* row0 = ap + (size_t)r_lo * KP + col;
        *(__nv_bfloat162*)(row0)           = hp0;
        *(__nv_bfloat162*)(row0 + HID)     = lp0;
        *(__nv_bfloat162*)(row0 + 2 * HID) = hp0;

        __nv_bfloat16 hx2 = __float2bfloat16(x2);
        __nv_bfloat16 hx3 = __float2bfloat16(x3);
        __nv_bfloat162 hp1(hx2, hx3);
        __nv_bfloat162 lp1(__float2bfloat16(x2 - __bfloat162float(hx2)),
                           __float2bfloat16(x3 - __bfloat162float(hx3)));
        __nv_bfloat16* row1 = ap + (size_t)r_hi * KP + col;
        *(__nv_bfloat162*)(row1)           = hp1;
        *(__nv_bfloat162*)(row1 + HID)     = lp1;
        *(__nv_bfloat162*)(row1 + 2 * HID) = hp1;
    }
}

// ===========================================================================
// Launch
// ===========================================================================
extern "C" void kernel_launch(void* const* d_in, const int* in_sizes, int n_in,
                              void* d_out, int out_size)
{
    const float* hidden = (const float*)d_in[0];
    const float* cosb   = (const float*)d_in[1];
    const float* sinb   = (const float*)d_in[2];
    const float* Wqkv   = (const float*)d_in[3];
    const float* bqkv   = (const float*)d_in[4];
    const float* Wout   = (const float*)d_in[5];
    const float* bout   = (const float*)d_in[6];
    float* out = (float*)d_out;

    float *qkv;
    __nv_bfloat16 *ap, *wqp, *wop, *qp, *kp2;
    __half *vh;
    cudaGetSymbolAddress((void**)&qkv, g_qkv);
    cudaGetSymbolAddress((void**)&ap, g_ap);
    cudaGetSymbolAddress((void**)&wqp, g_wqp);
    cudaGetSymbolAddress((void**)&wop, g_wop);
    cudaGetSymbolAddress((void**)&qp, g_qp);
    cudaGetSymbolAddress((void**)&kp2, g_kp2);
    cudaGetSymbolAddress((void**)&vh, g_vh);

    cudaFuncSetAttribute(mma_gemm, cudaFuncAttributeMaxDynamicSharedMemorySize, GEMM_SMEM);
    cudaFuncSetAttribute(attn_mma, cudaFuncAttributeMaxDynamicSharedMemorySize, ATT_SMEM);

    int n4 = S_TOT * HID / 4;

    // Prep: expanded bf16x3 operands
    split_A3<<<(n4 + 255) / 256, 256>>>((const float4*)hidden, ap, n4);
    dim3 tb(32, 8);
    split_T3<<<dim3(H3 / 32, HID / 32), tb>>>(Wqkv, wqp, H3);
    split_T3<<<dim3(HID / 32, HID / 32), tb>>>(Wout, wop, HID);

    // 1) QKV projection + bias (tensor cores)
    mma_gemm<<<dim3(H3 / 128, S_TOT / 128), 256, GEMM_SMEM>>>(ap, wqp, bqkv, qkv, H3);

    // 2) RoPE + attention-operand split
    int nrope = S_TOT * NH * 36;
    rope_split<<<(nrope + 255) / 256, 256>>>(qkv, cosb, sinb, qp, kp2, vh);

    // 3) Attention (tensor cores) -> writes bf16x3 ctx into g_ap
    dim3 ga(8, NH, NSEG);
    attn_mma<<<ga, 256, ATT_SMEM>>>(qp, kp2, vh, ap);

    // 4) Output projection + bias (tensor cores)
    mma_gemm<<<dim3(HID / 128, S_TOT / 128), 256, GEMM_SMEM>>>(ap, wop, bout, out, HID);
}

// round 7
// speedup vs baseline: 2.9821x; 1.1965x over previous
#include <cuda_runtime.h>
#include <cuda_bf16.h>
#include <cuda_fp16.h>
#include <cstdint>
#include <cstddef>

// Problem constants
#define S_TOT  8192
#define HID    1152
#define NH     16
#define HD     72
#define NSEG   8
#define LSEG   1024
#define H3     3456
#define ATT_SCALE 0.11785113019775793f   // 72^-0.5
#define KP     3456                      // expanded K' = 3*1152 (bf16x3 folded into K)
#define NST    (KP / 32)                 // 108 k-stages of 32
#define QKP    224                       // attention Q'/K' depth: 3*72=216 pad to 224

// Scratch (allocation-free rule: __device__ globals)
__device__ float g_qkv[(size_t)S_TOT * H3];              // 113 MB
__device__ __nv_bfloat16 g_ap[(size_t)S_TOT * KP];       // A' [M][3K]
__device__ __nv_bfloat16 g_wqp[(size_t)H3 * KP];         // Wqkv'T
__device__ __nv_bfloat16 g_wop[(size_t)HID * KP];        // Wout'T
__device__ __nv_bfloat16 g_qp[(size_t)S_TOT * NH * QKP]; // Q' [s][h][224]
__device__ __nv_bfloat16 g_kp2[(size_t)S_TOT * NH * QKP];// K' [s][h][224]
__device__ __half        g_vh[(size_t)S_TOT * NH * 80];  // V fp16 [s][h][80]

// ===========================================================================
// PTX helpers (portable sm_80-class only — no tcgen05 on compute_103)
// ===========================================================================
__device__ __forceinline__ uint32_t smem_u32(const void* p) {
    uint32_t a;
    asm("{ .reg .u64 t; cvta.to.shared.u64 t, %1; cvt.u32.u64 %0, t; }"
        : "=r"(a) : "l"(p));
    return a;
}
__device__ __forceinline__ void cp_async16(uint32_t s, const void* g) {
    asm volatile("cp.async.cg.shared.global [%0], [%1], 16;" :: "r"(s), "l"(g));
}
#define CP_COMMIT() asm volatile("cp.async.commit_group;" ::: "memory")
#define CP_WAIT0()  asm volatile("cp.async.wait_group 0;" ::: "memory")
#define CP_WAIT1()  asm volatile("cp.async.wait_group 1;" ::: "memory")

__device__ __forceinline__ void ldm_x4(uint32_t addr, uint32_t& r0, uint32_t& r1,
                                       uint32_t& r2, uint32_t& r3) {
    asm volatile("ldmatrix.sync.aligned.m8n8.x4.shared.b16 {%0,%1,%2,%3}, [%4];"
                 : "=r"(r0), "=r"(r1), "=r"(r2), "=r"(r3) : "r"(addr));
}
__device__ __forceinline__ void ldm_x4_t(uint32_t addr, uint32_t& r0, uint32_t& r1,
                                         uint32_t& r2, uint32_t& r3) {
    asm volatile("ldmatrix.sync.aligned.m8n8.x4.trans.shared.b16 {%0,%1,%2,%3}, [%4];"
                 : "=r"(r0), "=r"(r1), "=r"(r2), "=r"(r3) : "r"(addr));
}
__device__ __forceinline__ void mma16816(float* c, uint32_t a0, uint32_t a1,
                                         uint32_t a2, uint32_t a3,
                                         uint32_t b0, uint32_t b1) {
    asm volatile(
        "mma.sync.aligned.m16n8k16.row.col.f32.bf16.bf16.f32 "
        "{%0,%1,%2,%3}, {%4,%5,%6,%7}, {%8,%9}, {%0,%1,%2,%3};"
        : "+f"(c[0]), "+f"(c[1]), "+f"(c[2]), "+f"(c[3])
        : "r"(a0), "r"(a1), "r"(a2), "r"(a3), "r"(b0), "r"(b1));
}
__device__ __forceinline__ void mma16816h(float* c, uint32_t a0, uint32_t a1,
                                          uint32_t a2, uint32_t a3,
                                          uint32_t b0, uint32_t b1) {
    asm volatile(
        "mma.sync.aligned.m16n8k16.row.col.f32.f16.f16.f32 "
        "{%0,%1,%2,%3}, {%4,%5,%6,%7}, {%8,%9}, {%0,%1,%2,%3};"
        : "+f"(c[0]), "+f"(c[1]), "+f"(c[2]), "+f"(c[3])
        : "r"(a0), "r"(a1), "r"(a2), "r"(a3), "r"(b0), "r"(b1));
}

// ===========================================================================
// Prep: A' = [Ahi | Alo | Ahi] along K.  Input [M][1152] fp32.
// ===========================================================================
__global__ void split_A3(const float4* __restrict__ X, __nv_bfloat16* __restrict__ ap,
                         int n4)
{
    int i = blockIdx.x * blockDim.x + threadIdx.x;
    if (i >= n4) return;
    int m  = i / (HID / 4);
    int k  = (i % (HID / 4)) * 4;
    float4 x = X[i];
    __nv_bfloat16 h0 = __float2bfloat16(x.x);
    __nv_bfloat16 h1 = __float2bfloat16(x.y);
    __nv_bfloat16 h2 = __float2bfloat16(x.z);
    __nv_bfloat16 h3 = __float2bfloat16(x.w);
    __nv_bfloat16 l0 = __float2bfloat16(x.x - __bfloat162float(h0));
    __nv_bfloat16 l1 = __float2bfloat16(x.y - __bfloat162float(h1));
    __nv_bfloat16 l2 = __float2bfloat16(x.z - __bfloat162float(h2));
    __nv_bfloat16 l3 = __float2bfloat16(x.w - __bfloat162float(h3));
    __nv_bfloat162 hA(h0, h1), hB(h2, h3), lA(l0, l1), lB(l2, l3);
    __nv_bfloat162* p = (__nv_bfloat162*)(ap + (size_t)m * KP + k);
    p[0] = hA; p[1] = hB;
    *(__nv_bfloat162*)((__nv_bfloat16*)p + HID)         = lA;
    *(__nv_bfloat162*)((__nv_bfloat16*)p + HID + 2)     = lB;
    *(__nv_bfloat162*)((__nv_bfloat16*)p + 2 * HID)     = hA;
    *(__nv_bfloat162*)((__nv_bfloat16*)p + 2 * HID + 2) = hB;
}

// Prep: B'T = [Bhi | Bhi | Blo] along K, transposed.
__global__ void split_T3(const float* __restrict__ W, __nv_bfloat16* __restrict__ bp,
                         int Nd)
{
    __shared__ float tile[32][33];
    int n0 = blockIdx.x * 32, k0 = blockIdx.y * 32;
    int tx = threadIdx.x, ty = threadIdx.y;   // 32 x 8
    for (int i = ty; i < 32; i += 8)
        tile[i][tx] = W[(size_t)(k0 + i) * Nd + n0 + tx];
    __syncthreads();
    for (int i = ty; i < 32; i += 8) {
        float x = tile[tx][i];
        __nv_bfloat16 h = __float2bfloat16(x);
        __nv_bfloat16 l = __float2bfloat16(x - __bfloat162float(h));
        __nv_bfloat16* row = bp + (size_t)(n0 + i) * KP;
        row[k0 + tx]           = h;
        row[HID + k0 + tx]     = h;
        row[2 * HID + k0 + tx] = l;
    }
}

// ===========================================================================
// bf16 mma.sync GEMM: C[M,N] = A'[M,KP] @ B'T[N,KP] + bias[N]
// 128x128 block, 4 warps (warp tile 64x64), BK=32, 3-stage cp.async ring,
// one __syncthreads per stage, 2 blocks/SM.
// ===========================================================================
#define STAGE_B 20480                 // A (10240) + B (10240) per stage
#define GEMM_SMEM (3 * STAGE_B)       // 61,440 B

__global__ __launch_bounds__(128, 2) void mma_gemm(
    const __nv_bfloat16* __restrict__ Ap, const __nv_bfloat16* __restrict__ Bp,
    const float* __restrict__ bias, float* __restrict__ C, int N)
{
    extern __shared__ __align__(16) char sm[];

    const int t    = threadIdx.x;
    const int wid  = t >> 5;
    const int lane = t & 31;
    const int wm   = wid & 1;          // M half (64 rows)
    const int wn   = wid >> 1;         // N half (64 cols)
    const int m0   = blockIdx.y * 128;
    const int n0   = blockIdx.x * 128;

    const uint32_t sbase = smem_u32(sm);

    float c[4][8][4];
#pragma unroll
    for (int i = 0; i < 4; i++)
#pragma unroll
        for (int j = 0; j < 8; j++)
#pragma unroll
            for (int q = 0; q < 4; q++) c[i][j][q] = 0.f;

    // one stage: A 128 rows x 32 bf16 (80B-strided rows), B likewise at +10240
    auto load_stage = [&](int st, int k0) {
        uint32_t sA = sbase + st * STAGE_B;
        uint32_t sB = sA + 10240;
#pragma unroll
        for (int rep = 0; rep < 4; rep++) {
            int cidx = t + rep * 128;          // 0..511
            int row = cidx >> 2;
            int seg = cidx & 3;
            uint32_t soff = (uint32_t)(row * 80 + seg * 16);
            cp_async16(sA + soff, Ap + (size_t)(m0 + row) * KP + k0 + seg * 8);
            cp_async16(sB + soff, Bp + (size_t)(n0 + row) * KP + k0 + seg * 8);
        }
    };

    load_stage(0, 0);  CP_COMMIT();
    load_stage(1, 32); CP_COMMIT();

    const int arow = lane & 15;
    const int acol = (lane >> 4) * 16;
    const int bg   = lane >> 3;
    const int brow = lane & 7;
    const int bnt  = bg >> 1;
    const int bkh  = (bg & 1) * 16;

    int cur = 0;
    for (int kt = 0; kt < NST; kt++) {
        CP_WAIT1();                 // stage kt complete (only newest may pend)
        __syncthreads();

        int pf = cur + 2; if (pf >= 3) pf -= 3;
        if (kt + 2 < NST) load_stage(pf, (kt + 2) * 32);
        CP_COMMIT();                // always commit (constant group count)

        const uint32_t sA = sbase + cur * STAGE_B;
        const uint32_t sB = sA + 10240;

#pragma unroll
        for (int kk = 0; kk < 2; kk++) {
            const int kb = kk * 32;
            uint32_t a[4][4];
#pragma unroll
            for (int mt = 0; mt < 4; mt++) {
                uint32_t addr = sA
                    + (uint32_t)((wm * 64 + mt * 16 + arow) * 80 + kb + acol);
                ldm_x4(addr, a[mt][0], a[mt][1], a[mt][2], a[mt][3]);
            }
            uint32_t b[8][2];
#pragma unroll
            for (int p = 0; p < 4; p++) {
                uint32_t addr = sB
                    + (uint32_t)((wn * 64 + p * 16 + bnt * 8 + brow) * 80 + kb + bkh);
                uint32_t r0, r1, r2, r3;
                ldm_x4(addr, r0, r1, r2, r3);
                b[p * 2][0] = r0; b[p * 2][1] = r1;
                b[p * 2 + 1][0] = r2; b[p * 2 + 1][1] = r3;
            }
#pragma unroll
            for (int mt = 0; mt < 4; mt++)
#pragma unroll
                for (int nt = 0; nt < 8; nt++)
                    mma16816(c[mt][nt], a[mt][0], a[mt][1], a[mt][2], a[mt][3],
                             b[nt][0], b[nt][1]);
        }
        cur++; if (cur == 3) cur = 0;
    }

    const int qrow = lane >> 2;
    const int qcol = (lane & 3) * 2;
#pragma unroll
    for (int nt = 0; nt < 8; nt++) {
        int col = n0 + wn * 64 + nt * 8 + qcol;
        float b0 = bias[col], b1 = bias[col + 1];
#pragma unroll
        for (int mt = 0; mt < 4; mt++) {
            int r0 = m0 + wm * 64 + mt * 16 + qrow;
            float2 v0 = make_float2(c[mt][nt][0] + b0, c[mt][nt][1] + b1);
            float2 v1 = make_float2(c[mt][nt][2] + b0, c[mt][nt][3] + b1);
            *(float2*)(C + (size_t)r0 * N + col)       = v0;
            *(float2*)(C + (size_t)(r0 + 8) * N + col) = v1;
        }
    }
}

// ===========================================================================
// RoPE + split for attention operands (Q'/K' bf16x3, V fp16)
// ===========================================================================
__global__ void rope_split(const float* __restrict__ qkv,
                           const float* __restrict__ cosb,
                           const float* __restrict__ sinb,
                           __nv_bfloat16* __restrict__ qp,
                           __nv_bfloat16* __restrict__ kp,
                           __half* __restrict__ vh)
{
    int idx = blockIdx.x * blockDim.x + threadIdx.x;
    if (idx >= S_TOT * NH * 36) return;
    int d   = idx % 36;
    int tmp = idx / 36;
    int h   = tmp % NH;
    int s   = tmp / NH;

    float c  = cosb[s * HD + d];
    float sn = sinb[s * HD + d];
    size_t ib = (size_t)s * H3 + h * HD + d;

    float q0 = qkv[ib], q1 = qkv[ib + 36];
    float rq0 = (q0 * c - q1 * sn) * ATT_SCALE;
    float rq1 = (q1 * c + q0 * sn) * ATT_SCALE;
    float k0 = qkv[ib + HID], k1 = qkv[ib + HID + 36];
    float rk0 = k0 * c - k1 * sn;
    float rk1 = k1 * c + k0 * sn;
    float v0 = qkv[ib + 2 * HID], v1 = qkv[ib + 2 * HID + 36];

    size_t ob = ((size_t)s * NH + h) * QKP;
    __nv_bfloat16 hq0 = __float2bfloat16(rq0);
    __nv_bfloat16 hq1 = __float2bfloat16(rq1);
    __nv_bfloat16 lq0 = __float2bfloat16(rq0 - __bfloat162float(hq0));
    __nv_bfloat16 lq1 = __float2bfloat16(rq1 - __bfloat162float(hq1));
    qp[ob + d]            = hq0;
    qp[ob + d + 36]       = hq1;
    qp[ob + 72 + d]       = lq0;
    qp[ob + 72 + d + 36]  = lq1;
    qp[ob + 144 + d]      = hq0;
    qp[ob + 144 + d + 36] = hq1;

    __nv_bfloat16 hk0 = __float2bfloat16(rk0);
    __nv_bfloat16 hk1 = __float2bfloat16(rk1);
    __nv_bfloat16 lk0 = __float2bfloat16(rk0 - __bfloat162float(hk0));
    __nv_bfloat16 lk1 = __float2bfloat16(rk1 - __bfloat162float(hk1));
    kp[ob + d]            = hk0;
    kp[ob + d + 36]       = hk1;
    kp[ob + 72 + d]       = hk0;
    kp[ob + 72 + d + 36]  = hk1;
    kp[ob + 144 + d]      = lk0;
    kp[ob + 144 + d + 36] = lk1;

    size_t vb = ((size_t)s * NH + h) * 80;
    vh[vb + d]      = __float2half(v0);
    vh[vb + d + 36] = __float2half(v1);

    if (d < 8) {
        __nv_bfloat16 z = __float2bfloat16(0.f);
        qp[ob + 216 + d] = z;
        kp[ob + 216 + d] = z;
        vh[vb + 72 + d]  = __float2half(0.f);
    }
}

// ===========================================================================
// FA2-style mma attention; epilogue writes bf16x3 split DIRECTLY into g_ap
// ===========================================================================
#define SQ_BYTES (128 * 464)
#define SK_BYTES (64 * 464)
#define SV_BYTES (64 * 176)
#define ATT_SMEM (SQ_BYTES + 2 * SK_BYTES + 2 * SV_BYTES)

__global__ __launch_bounds__(256, 1) void attn_mma(
    const __nv_bfloat16* __restrict__ Qp, const __nv_bfloat16* __restrict__ Kp,
    const __half* __restrict__ Vh, __nv_bfloat16* __restrict__ ap)
{
    extern __shared__ char smA[];
    char* sQ = smA;
    char* sK = smA + SQ_BYTES;
    char* sV = smA + SQ_BYTES + 2 * SK_BYTES;

    const int t    = threadIdx.x;
    const int lane = t & 31;
    const int wid  = t >> 5;
    const int qt   = blockIdx.x;     // 0..7
    const int h    = blockIdx.y;     // 0..15
    const int seg  = blockIdx.z;     // 0..7
    const int sbase = seg * LSEG;
    const int qbase = sbase + qt * 128;
    const int q0    = wid * 16;

    auto load_q = [&]() {
        for (int c = t; c < 128 * 28; c += 256) {
            int row = c / 28, ch = c % 28;
            cp_async16(smem_u32(sQ + row * 464 + ch * 16),
                       Qp + ((size_t)(qbase + row) * NH + h) * QKP + ch * 8);
        }
    };
    auto load_kv = [&](int st, int kb) {
        char* dk = sK + st * SK_BYTES;
        char* dv = sV + st * SV_BYTES;
        for (int c = t; c < 64 * 28 + 64 * 10; c += 256) {
            if (c < 1792) {
                int row = c / 28, ch = c % 28;
                cp_async16(smem_u32(dk + row * 464 + ch * 16),
                           Kp + ((size_t)(sbase + kb + row) * NH + h) * QKP + ch * 8);
            } else {
                int c2 = c - 1792;
                int row = c2 / 10, ch = c2 % 10;
                cp_async16(smem_u32(dv + row * 176 + ch * 16),
                           Vh + ((size_t)(sbase + kb + row) * NH + h) * 80 + ch * 8);
            }
        }
    };

    load_q(); load_kv(0, 0); CP_COMMIT();
    load_kv(1, 64); CP_COMMIT();

    uint32_t qf[14][4];
    float o[10][4];
#pragma unroll
    for (int j = 0; j < 10; j++)
#pragma unroll
        for (int q = 0; q < 4; q++) o[j][q] = 0.f;
    float m0v = -1e30f, m1v = -1e30f, l0v = 0.f, l1v = 0.f;

    const int qlrow = lane % 16;
    const int qlcol = (lane / 16) * 16;
    const int bkey  = (lane / 16) * 8 + (lane % 8);
    const int bkoff = ((lane / 8) & 1) * 16;
    const int vkey  = ((lane / 8) & 1) * 8 + (lane % 8);
    const int vdoff = (lane / 16) * 16;

    for (int kt = 0; kt < 16; kt++) {
        if (kt == 15) { CP_WAIT0(); } else { CP_WAIT1(); }
        __syncthreads();

        if (kt == 0) {
#pragma unroll
            for (int kk = 0; kk < 14; kk++) {
                uint32_t addr = smem_u32(sQ + (q0 + qlrow) * 464 + kk * 32 + qlcol);
                ldm_x4(addr, qf[kk][0], qf[kk][1], qf[kk][2], qf[kk][3]);
            }
        }

        const char* bk = sK + (kt & 1) * SK_BYTES;
        const char* bv = sV + (kt & 1) * SV_BYTES;

        float s[8][4];
#pragma unroll
        for (int j = 0; j < 8; j++)
#pragma unroll
            for (int q = 0; q < 4; q++) s[j][q] = 0.f;

#pragma unroll
        for (int kk = 0; kk < 14; kk++) {
#pragma unroll
            for (int pr = 0; pr < 4; pr++) {
                uint32_t addr = smem_u32(bk + (pr * 16 + bkey) * 464 + kk * 32 + bkoff);
                uint32_t r0, r1, r2, r3;
                ldm_x4(addr, r0, r1, r2, r3);
                mma16816(s[pr * 2],     qf[kk][0], qf[kk][1], qf[kk][2], qf[kk][3], r0, r1);
                mma16816(s[pr * 2 + 1], qf[kk][0], qf[kk][1], qf[kk][2], qf[kk][3], r2, r3);
            }
        }

        float rx0 = -1e30f, rx1 = -1e30f;
#pragma unroll
        for (int j = 0; j < 8; j++) {
            rx0 = fmaxf(rx0, fmaxf(s[j][0], s[j][1]));
            rx1 = fmaxf(rx1, fmaxf(s[j][2], s[j][3]));
        }
        rx0 = fmaxf(rx0, __shfl_xor_sync(0xffffffffu, rx0, 1));
        rx0 = fmaxf(rx0, __shfl_xor_sync(0xffffffffu, rx0, 2));
        rx1 = fmaxf(rx1, __shfl_xor_sync(0xffffffffu, rx1, 1));
        rx1 = fmaxf(rx1, __shfl_xor_sync(0xffffffffu, rx1, 2));

        float mn0 = fmaxf(m0v, rx0), mn1 = fmaxf(m1v, rx1);
        float a0 = __expf(m0v - mn0), a1 = __expf(m1v - mn1);
        m0v = mn0; m1v = mn1;

        float sum0 = 0.f, sum1 = 0.f;
#pragma unroll
        for (int j = 0; j < 8; j++) {
            s[j][0] = __expf(s[j][0] - mn0);
            s[j][1] = __expf(s[j][1] - mn0);
            s[j][2] = __expf(s[j][2] - mn1);
            s[j][3] = __expf(s[j][3] - mn1);
            sum0 += s[j][0] + s[j][1];
            sum1 += s[j][2] + s[j][3];
        }
        sum0 += __shfl_xor_sync(0xffffffffu, sum0, 1);
        sum0 += __shfl_xor_sync(0xffffffffu, sum0, 2);
        sum1 += __shfl_xor_sync(0xffffffffu, sum1, 1);
        sum1 += __shfl_xor_sync(0xffffffffu, sum1, 2);
        l0v = l0v * a0 + sum0;
        l1v = l1v * a1 + sum1;

#pragma unroll
        for (int j = 0; j < 10; j++) {
            o[j][0] *= a0; o[j][1] *= a0;
            o[j][2] *= a1; o[j][3] *= a1;
        }

        uint32_t pa[4][4];
#pragma unroll
        for (int kk2 = 0; kk2 < 4; kk2++) {
            int j = 2 * kk2;
            __half2 h0 = __floats2half2_rn(s[j][0],     s[j][1]);
            __half2 h1 = __floats2half2_rn(s[j][2],     s[j][3]);
            __half2 h2 = __floats2half2_rn(s[j + 1][0], s[j + 1][1]);
            __half2 h3 = __floats2half2_rn(s[j + 1][2], s[j + 1][3]);
            pa[kk2][0] = *(uint32_t*)&h0;
            pa[kk2][1] = *(uint32_t*)&h1;
            pa[kk2][2] = *(uint32_t*)&h2;
            pa[kk2][3] = *(uint32_t*)&h3;
        }

#pragma unroll
        for (int kk2 = 0; kk2 < 4; kk2++) {
#pragma unroll
            for (int vp = 0; vp < 5; vp++) {
                uint32_t addr = smem_u32(bv + (kk2 * 16 + vkey) * 176 + vp * 32 + vdoff);
                uint32_t r0, r1, r2, r3;
                ldm_x4_t(addr, r0, r1, r2, r3);
                mma16816h(o[vp * 2],     pa[kk2][0], pa[kk2][1], pa[kk2][2], pa[kk2][3], r0, r1);
                mma16816h(o[vp * 2 + 1], pa[kk2][0], pa[kk2][1], pa[kk2][2], pa[kk2][3], r2, r3);
            }
        }

        __syncthreads();
        if (kt + 2 < 16) {
            load_kv(kt & 1, (kt + 2) * 64);
            CP_COMMIT();
        }
    }

    // ---- store bf16x3 split directly into A' rows (dims 0..71 only) ----
    float inv0 = 1.f / l0v, inv1 = 1.f / l1v;
    int r_lo = qbase + q0 + lane / 4;
    int r_hi = r_lo + 8;
#pragma unroll
    for (int j = 0; j < 9; j++) {
        int col = h * HD + j * 8 + (lane & 3) * 2;
        float x0 = o[j][0] * inv0, x1 = o[j][1] * inv0;
        float x2 = o[j][2] * inv1, x3 = o[j][3] * inv1;

        __nv_bfloat16 hx0 = __float2bfloat16(x0);
        __nv_bfloat16 hx1 = __float2bfloat16(x1);
        __nv_bfloat162 hp0(hx0, hx1);
        __nv_bfloat162 lp0(__float2bfloat16(x0 - __bfloat162float(hx0)),
                           __float2bfloat16(x1 - __bfloat162float(hx1)));
        __nv_bfloat16* row0 = ap + (size_t)r_lo * KP + col;
        *(__nv_bfloat162*)(row0)           = hp0;
        *(__nv_bfloat162*)(row0 + HID)     = lp0;
        *(__nv_bfloat162*)(row0 + 2 * HID) = hp0;

        __nv_bfloat16 hx2 = __float2bfloat16(x2);
        __nv_bfloat16 hx3 = __float2bfloat16(x3);
        __nv_bfloat162 hp1(hx2, hx3);
        __nv_bfloat162 lp1(__float2bfloat16(x2 - __bfloat162float(hx2)),
                           __float2bfloat16(x3 - __bfloat162float(hx3)));
        __nv_bfloat16* row1 = ap + (size_t)r_hi * KP + col;
        *(__nv_bfloat162*)(row1)           = hp1;
        *(__nv_bfloat162*)(row1 + HID)     = lp1;
        *(__nv_bfloat162*)(row1 + 2 * HID) = hp1;
    }
}

// ===========================================================================
// Launch
// ===========================================================================
extern "C" void kernel_launch(void* const* d_in, const int* in_sizes, int n_in,
                              void* d_out, int out_size)
{
    const float* hidden = (const float*)d_in[0];
    const float* cosb   = (const float*)d_in[1];
    const float* sinb   = (const float*)d_in[2];
    const float* Wqkv   = (const float*)d_in[3];
    const float* bqkv   = (const float*)d_in[4];
    const float* Wout   = (const float*)d_in[5];
    const float* bout   = (const float*)d_in[6];
    float* out = (float*)d_out;

    float *qkv;
    __nv_bfloat16 *ap, *wqp, *wop, *qp, *kp2;
    __half *vh;
    cudaGetSymbolAddress((void**)&qkv, g_qkv);
    cudaGetSymbolAddress((void**)&ap, g_ap);
    cudaGetSymbolAddress((void**)&wqp, g_wqp);
    cudaGetSymbolAddress((void**)&wop, g_wop);
    cudaGetSymbolAddress((void**)&qp, g_qp);
    cudaGetSymbolAddress((void**)&kp2, g_kp2);
    cudaGetSymbolAddress((void**)&vh, g_vh);

    cudaFuncSetAttribute(mma_gemm, cudaFuncAttributeMaxDynamicSharedMemorySize, GEMM_SMEM);
    cudaFuncSetAttribute(attn_mma, cudaFuncAttributeMaxDynamicSharedMemorySize, ATT_SMEM);

    int n4 = S_TOT * HID / 4;

    // Prep: expanded bf16x3 operands
    split_A3<<<(n4 + 255) / 256, 256>>>((const float4*)hidden, ap, n4);
    dim3 tb(32, 8);
    split_T3<<<dim3(H3 / 32, HID / 32), tb>>>(Wqkv, wqp, H3);
    split_T3<<<dim3(HID / 32, HID / 32), tb>>>(Wout, wop, HID);

    // 1) QKV projection + bias (tensor cores)
    mma_gemm<<<dim3(H3 / 128, S_TOT / 128), 128, GEMM_SMEM>>>(ap, wqp, bqkv, qkv, H3);

    // 2) RoPE + attention-operand split
    int nrope = S_TOT * NH * 36;
    rope_split<<<(nrope + 255) / 256, 256>>>(qkv, cosb, sinb, qp, kp2, vh);

    // 3) Attention (tensor cores) -> writes bf16x3 ctx into g_ap
    dim3 ga(8, NH, NSEG);
    attn_mma<<<ga, 256, ATT_SMEM>>>(qp, kp2, vh, ap);

    // 4) Output projection + bias (tensor cores)
    mma_gemm<<<dim3(HID / 128, S_TOT / 128), 128, GEMM_SMEM>>>(ap, wop, bout, out, HID);
}